// round 4
// baseline (speedup 1.0000x reference)
#include <cuda_runtime.h>
#include <math.h>

// ---------------- static problem config ----------------
#define NNODES   102400
#define NEDGES   819200
#define NBATCH   16
#define GCELLS   72
#define GXDIM    8
#define PSX      16.0f
#define PSY      12.0f
#define FC_IN    2304
#define NTILES   12800           // NNODES / 8
#define NBLK     444             // 148 SMs * 3 blocks (full co-residency)
#define NTHR     256

// ---------------- scratch (device globals; no allocation) ----------------
__device__ float    g_basis[(size_t)NEDGES * 8];   // pre-scaled by 1/deg(dst)
__device__ int      g_srcs [NEDGES];
__device__ int      g_cnt  [NNODES];
__device__ int      g_rowp [NNODES + 1];
__device__ int      g_wcur [NNODES];
__device__ float    g_invc [NNODES];
__device__ float    g_bufA [(size_t)NNODES * 32];
__device__ float    g_bufB [(size_t)NNODES * 32];
__device__ float    g_bufC [(size_t)NNODES * 32];
__device__ unsigned g_pool [NBATCH * GCELLS * 32];
__device__ int      g_bsum [128];
__device__ unsigned g_bar_gen;
__device__ unsigned g_bar_cnt;

// ---------------- packed fp32x2 helpers (sm_103a FFMA2) ----------------
typedef unsigned long long u64;
__device__ __forceinline__ u64 pack2(float lo, float hi) {
    u64 r;
    asm("mov.b64 %0, {%1,%2};" : "=l"(r)
        : "r"(__float_as_uint(lo)), "r"(__float_as_uint(hi)));
    return r;
}
__device__ __forceinline__ float2 unpack2(u64 v) {
    unsigned lo, hi;
    asm("mov.b64 {%0,%1}, %2;" : "=r"(lo), "=r"(hi) : "l"(v));
    return make_float2(__uint_as_float(lo), __uint_as_float(hi));
}
__device__ __forceinline__ u64 fma2(u64 a, u64 b, u64 c) {
    u64 d;
    asm("fma.rn.f32x2 %0, %1, %2, %3;" : "=l"(d) : "l"(a), "l"(b), "l"(c));
    return d;
}
__device__ __forceinline__ unsigned enc_f32(float f) {
    unsigned u = __float_as_uint(f);
    return (u & 0x80000000u) ? ~u : (u | 0x80000000u);
}
__device__ __forceinline__ float fast_elu(float o) {
    return (o > 0.f) ? o : (__expf(o) - 1.0f);
}

// ---------------- software grid barrier ----------------
__device__ __forceinline__ void grid_barrier(unsigned target) {
    __threadfence();
    __syncthreads();
    if (threadIdx.x == 0) {
        unsigned my = atomicAdd(&g_bar_cnt, 1u);
        if (my == NBLK - 1u) {
            g_bar_cnt = 0u;
            __threadfence();
            atomicExch(&g_bar_gen, target);
        } else {
            while (*(volatile unsigned*)&g_bar_gen < target) { __nanosleep(64); }
        }
    }
    __syncthreads();
}

// ---------------- conv1 phase (Cin=1 -> Cout=8) ----------------
__device__ void conv1_phase(const float* __restrict__ x, float* __restrict__ hout,
                            const float* __restrict__ W) {
    int tid = threadIdx.x, lane = tid & 31, w = tid >> 5;
    float wreg[8];
#pragma unroll
    for (int k = 0; k < 8; k++) wreg[k] = __ldg(&W[k * 8 + (lane & 7)]);
    for (int node = blockIdx.x * 8 + w; node < NNODES; node += NBLK * 8) {
        int beg = g_rowp[node], end = g_rowp[node + 1];
        float a[8] = {0, 0, 0, 0, 0, 0, 0, 0};
        for (int e = beg + lane; e < end; e += 32) {
            float xv = __ldg(&x[g_srcs[e]]);
            const float4* bp = (const float4*)(g_basis + (size_t)e * 8);
            float4 b0 = __ldg(bp), b1 = __ldg(bp + 1);
            a[0] = fmaf(b0.x, xv, a[0]); a[1] = fmaf(b0.y, xv, a[1]);
            a[2] = fmaf(b0.z, xv, a[2]); a[3] = fmaf(b0.w, xv, a[3]);
            a[4] = fmaf(b1.x, xv, a[4]); a[5] = fmaf(b1.y, xv, a[5]);
            a[6] = fmaf(b1.z, xv, a[6]); a[7] = fmaf(b1.w, xv, a[7]);
        }
#pragma unroll
        for (int k = 0; k < 8; k++)
#pragma unroll
            for (int off = 16; off; off >>= 1)
                a[k] += __shfl_xor_sync(0xffffffffu, a[k], off);
        if (lane < 8) {
            float o = 0.f;
#pragma unroll
            for (int k = 0; k < 8; k++) o = fmaf(a[k], wreg[k], o);
            hout[(size_t)node * 8 + lane] = fast_elu(o);   // basis pre-scaled by 1/deg
        }
    }
}

// ---------------- fused spline conv phase (Cin in {8,16,32}) ----------------
// Aggregation (warp = node): acc2[q] = u64 pair (agg[64q+lane], agg[64q+32+lane])
// stored to sA2[jp=q*32+lane][node]. GEMM: slice s owns jp-range; W j-pairs
// hoisted to registers ONCE per phase; per jp: 4 broadcast LDS.128 feed 8 FMA2
// over all 8 nodes. Partial (lo,hi) sums reduced across slices in epilogue.
template <int Cin, int Cout, bool POOL>
__device__ void conv_phase(const float* __restrict__ hin, float* __restrict__ hout,
                           const float* __restrict__ resid, const float* __restrict__ W,
                           const float* __restrict__ pos, const int* __restrict__ batch,
                           u64* sA2, u64* sPart) {
    constexpr int KC  = 8 * Cin;
    constexpr int RP  = KC / 64;            // u64 accs per lane: 1,2,4
    constexpr int JPH = KC / 2;             // j-pair rows: 32,64,128
    constexpr int SLC = (Cout == 32) ? 8 : 16;
    constexpr int JP2 = JPH / SLC;          // jp per slice: 2,4,8,16
    constexpr int PAD = 10;                 // u64 row stride (80B, 16B-aligned)

    int tid = threadIdx.x, lane = tid & 31, w = tid >> 5;
    int ci = lane & (Cin - 1);
    int hi16 = lane >> 4;
    int qq = (lane >> 3) & 3;
    int co = lane & (Cout - 1);
    int s = (Cout == 32) ? w : (w * 2 + hi16);

    // hoisted interleaved W pairs: w2reg[i] = (W[jlo,co], W[jlo+32,co])
    u64 w2reg[JP2];
#pragma unroll
    for (int i = 0; i < JP2; i++) {
        int jp = s * JP2 + i;
        int jlo = ((jp >> 5) << 6) + (jp & 31);
        w2reg[i] = pack2(__ldg(&W[jlo * Cout + co]),
                         __ldg(&W[(jlo + 32) * Cout + co]));
    }

    for (int tile = blockIdx.x; tile < NTILES; tile += NBLK) {
        int node = tile * 8 + w;
        int beg = g_rowp[node], end = g_rowp[node + 1];
        int deg = end - beg;

        // ---- aggregation ----
        u64 acc2[RP];
#pragma unroll
        for (int q = 0; q < RP; q++) acc2[q] = 0ull;
        int degc = deg < 32 ? deg : 32;
        int s_l = (lane < degc) ? g_srcs[beg + lane] : 0;

        for (int e0 = 0; e0 < degc; e0 += 2) {
            float xv[2]; float4 ba[2], bb[2];
#pragma unroll
            for (int u = 0; u < 2; u++) {
                int e = e0 + u;
                bool p = e < degc;
                int sidx = __shfl_sync(0xffffffffu, s_l, e & 31);
                xv[u] = p ? __ldg(&hin[(size_t)sidx * Cin + ci]) : 0.f;
                const float4* bp = (const float4*)(g_basis + (size_t)(beg + (p ? e : 0)) * 8);
                ba[u] = __ldg(bp); bb[u] = __ldg(bp + 1);
            }
#pragma unroll
            for (int u = 0; u < 2; u++) {
                u64 x2 = pack2(xv[u], xv[u]);
                float b[8] = {ba[u].x, ba[u].y, ba[u].z, ba[u].w,
                              bb[u].x, bb[u].y, bb[u].z, bb[u].w};
#pragma unroll
                for (int q = 0; q < RP; q++) {
                    float blo, bhi;
                    if (Cin == 32)      { blo = b[2 * q];     bhi = b[2 * q + 1]; }
                    else if (Cin == 16) { blo = hi16 ? b[4 * q + 1] : b[4 * q];
                                          bhi = hi16 ? b[4 * q + 3] : b[4 * q + 2]; }
                    else {
                        float t01 = (qq & 1) ? b[1] : b[0];
                        float t23 = (qq & 1) ? b[3] : b[2];
                        blo = (qq & 2) ? t23 : t01;
                        float u01 = (qq & 1) ? b[5] : b[4];
                        float u23 = (qq & 1) ? b[7] : b[6];
                        bhi = (qq & 2) ? u23 : u01;
                    }
                    acc2[q] = fma2(pack2(blo, bhi), x2, acc2[q]);
                }
            }
        }
        for (int e = 32; e < deg; e++) {          // rare high-degree tail
            int sidx = g_srcs[beg + e];
            float xv = __ldg(&hin[(size_t)sidx * Cin + ci]);
            const float4* bp = (const float4*)(g_basis + (size_t)(beg + e) * 8);
            float4 t0 = __ldg(bp), t1 = __ldg(bp + 1);
            u64 x2 = pack2(xv, xv);
            float b[8] = {t0.x, t0.y, t0.z, t0.w, t1.x, t1.y, t1.z, t1.w};
#pragma unroll
            for (int q = 0; q < RP; q++) {
                float blo, bhi;
                if (Cin == 32)      { blo = b[2 * q];     bhi = b[2 * q + 1]; }
                else if (Cin == 16) { blo = hi16 ? b[4 * q + 1] : b[4 * q];
                                      bhi = hi16 ? b[4 * q + 3] : b[4 * q + 2]; }
                else {
                    float t01 = (qq & 1) ? b[1] : b[0];
                    float t23 = (qq & 1) ? b[3] : b[2];
                    blo = (qq & 2) ? t23 : t01;
                    float u01 = (qq & 1) ? b[5] : b[4];
                    float u23 = (qq & 1) ? b[7] : b[6];
                    bhi = (qq & 2) ? u23 : u01;
                }
                acc2[q] = fma2(pack2(blo, bhi), x2, acc2[q]);
            }
        }
#pragma unroll
        for (int q = 0; q < RP; q++)
            sA2[(q * 32 + lane) * PAD + w] = acc2[q];
        __syncthreads();

        // ---- GEMM: slice s, j-pairs in registers, nodes via LDS.128 ----
        u64 acc[8];
#pragma unroll
        for (int n = 0; n < 8; n++) acc[n] = 0ull;
#pragma unroll
        for (int i = 0; i < JP2; i++) {
            int jp = s * JP2 + i;
            const u64* row = &sA2[jp * PAD];
#pragma unroll
            for (int m = 0; m < 4; m++) {
                ulonglong2 v = *(const ulonglong2*)&row[2 * m];
                acc[2 * m]     = fma2(v.x, w2reg[i], acc[2 * m]);
                acc[2 * m + 1] = fma2(v.y, w2reg[i], acc[2 * m + 1]);
            }
        }
#pragma unroll
        for (int n = 0; n < 8; n++)
            sPart[(s * 8 + n) * Cout + co] = acc[n];
        __syncthreads();

        // ---- reduce slices + epilogue ----
        if (tid < 8 * Cout) {
            int n = tid / Cout;
            int c = tid % Cout;
            float sum = 0.f;
#pragma unroll
            for (int ss = 0; ss < SLC; ss++) {
                float2 v = unpack2(sPart[(ss * 8 + n) * Cout + c]);
                sum += v.x + v.y;
            }
            int node2 = tile * 8 + n;
            float o = fast_elu(sum);                  // mean folded into basis
            if (resid) o += resid[(size_t)node2 * Cout + c];
            if (POOL) {
                float px = pos[node2 * 3 + 0], py = pos[node2 * 3 + 1];
                int cx = (int)floorf(px / PSX);
                int cy = (int)floorf(py / PSY);
                int cl = batch[node2] * GCELLS + cy * GXDIM + cx;
                atomicMax(&g_pool[cl * 32 + c], enc_f32(o));
            } else {
                hout[(size_t)node2 * Cout + c] = o;
            }
        }
        __syncthreads();
    }
}

// ---------------- the mega kernel ----------------
__global__ void __launch_bounds__(NTHR, 3)
k_mega(const float* __restrict__ x,   const float* __restrict__ pos,
       const float* __restrict__ ea,  const int* __restrict__ ei,
       const int* __restrict__ batch, const float* __restrict__ fcw,
       const float* __restrict__ w1, const float* __restrict__ w2,
       const float* __restrict__ w3, const float* __restrict__ w4,
       const float* __restrict__ w5, const float* __restrict__ w6,
       const float* __restrict__ w7, float* __restrict__ out) {
    __shared__ __align__(16) u64 sA2[128 * 10];     // 10.2 KB
    __shared__ __align__(16) u64 sPart[2048];       // 16 KB
    __shared__ int sScan[256];

    const int tid = threadIdx.x;
    const int gtid = blockIdx.x * NTHR + tid;
    const int* src = ei;
    const int* dst = ei + NEDGES;
    unsigned barbase = *(volatile unsigned*)&g_bar_gen;
    __syncthreads();

    // ---- P0: zero counters + pool ----
    for (int i = gtid; i < NNODES; i += NBLK * NTHR) g_cnt[i] = 0;
    for (int i = gtid; i < NBATCH * GCELLS * 32; i += NBLK * NTHR)
        g_pool[i] = 0x007FFFFFu;
    grid_barrier(barbase + 1);

    // ---- P1: degree count ----
    for (int e = gtid; e < NEDGES; e += NBLK * NTHR)
        atomicAdd(&g_cnt[dst[e]], 1);
    grid_barrier(barbase + 2);

    // ---- P2a: block-local scan (blocks 0..99) ----
    if (blockIdx.x < 100) {
        int b = blockIdx.x;
        int base = b * 1024 + tid * 4;
        int v0 = g_cnt[base + 0], v1 = g_cnt[base + 1];
        int v2 = g_cnt[base + 2], v3 = g_cnt[base + 3];
        int sv = v0 + v1 + v2 + v3;
        sScan[tid] = sv;
        __syncthreads();
        for (int off = 1; off < 256; off <<= 1) {
            int t = (tid >= off) ? sScan[tid - off] : 0;
            __syncthreads();
            sScan[tid] += t;
            __syncthreads();
        }
        int excl = sScan[tid] - sv;
        g_rowp[base + 0] = excl;
        g_rowp[base + 1] = excl + v0;
        g_rowp[base + 2] = excl + v0 + v1;
        g_rowp[base + 3] = excl + v0 + v1 + v2;
        if (tid == 255) g_bsum[b] = sScan[255];
    }
    grid_barrier(barbase + 3);

    // ---- P2b: scan of 100 block sums (block 0) ----
    if (blockIdx.x == 0) {
        int v = (tid < 100) ? g_bsum[tid] : 0;
        sScan[tid] = v;
        __syncthreads();
        for (int off = 1; off < 256; off <<= 1) {
            int a = (tid >= off) ? sScan[tid - off] : 0;
            __syncthreads();
            sScan[tid] += a;
            __syncthreads();
        }
        if (tid < 100) g_bsum[tid] = sScan[tid] - v;
    }
    grid_barrier(barbase + 4);

    // ---- P2c: global row pointers + inverse counts ----
    for (int i = gtid; i < NNODES; i += NBLK * NTHR) {
        int r = g_rowp[i] + g_bsum[i >> 10];
        g_rowp[i] = r;
        g_wcur[i] = r;
        int c = g_cnt[i];
        g_invc[i] = 1.0f / (float)(c > 0 ? c : 1);
    }
    if (gtid == 0) g_rowp[NNODES] = NEDGES;
    grid_barrier(barbase + 5);

    // ---- P3: CSR fill + basis (pre-scaled by 1/deg(dst) => mean folded) ----
    for (int e = gtid; e < NEDGES; e += NBLK * NTHR) {
        int d = dst[e];
        int p = atomicAdd(&g_wcur[d], 1);
        float ic = g_invc[d];
        g_srcs[p] = src[e];
        float u0 = fminf(fmaxf(ea[e * 3 + 0], 0.f), 1.f);
        float u1 = fminf(fmaxf(ea[e * 3 + 1], 0.f), 1.f);
        float u2 = fminf(fmaxf(ea[e * 3 + 2], 0.f), 1.f);
        float m0 = 1.f - u0, m1 = 1.f - u1, m2 = 1.f - u2;
        float c2m = ic * m2, c2u = ic * u2;
        float4 lo = make_float4(m0 * m1 * c2m, u0 * m1 * c2m, m0 * u1 * c2m, u0 * u1 * c2m);
        float4 hi = make_float4(m0 * m1 * c2u, u0 * m1 * c2u, m0 * u1 * c2u, u0 * u1 * c2u);
        float4* bo = (float4*)(g_basis + (size_t)p * 8);
        bo[0] = lo; bo[1] = hi;
    }
    grid_barrier(barbase + 6);

    // ---- P4..P10: seven conv layers ----
    conv1_phase(x, g_bufA, w1);
    grid_barrier(barbase + 7);
    conv_phase<8,  16, false>(g_bufA, g_bufB, nullptr, w2, pos, batch, sA2, sPart);
    grid_barrier(barbase + 8);
    conv_phase<16, 16, false>(g_bufB, g_bufA, nullptr, w3, pos, batch, sA2, sPart);
    grid_barrier(barbase + 9);
    conv_phase<16, 16, false>(g_bufA, g_bufC, g_bufB, w4, pos, batch, sA2, sPart);
    grid_barrier(barbase + 10);
    conv_phase<16, 32, false>(g_bufC, g_bufA, nullptr, w5, pos, batch, sA2, sPart);
    grid_barrier(barbase + 11);
    conv_phase<32, 32, false>(g_bufA, g_bufB, nullptr, w6, pos, batch, sA2, sPart);
    grid_barrier(barbase + 12);
    conv_phase<32, 32, true >(g_bufB, g_bufC, g_bufA, w7, pos, batch, sA2, sPart);
    grid_barrier(barbase + 13);

    // ---- P11: FC head (blocks 0..15) ----
    if (blockIdx.x < NBATCH) {
        int b = blockIdx.x;
        float a0 = 0.f, a1 = 0.f;
        for (int j = tid; j < FC_IN; j += NTHR) {
            unsigned u = g_pool[b * FC_IN + j];
            float v = (u & 0x80000000u) ? __uint_as_float(u & 0x7fffffffu)
                                        : __uint_as_float(~u);
            if (!isfinite(v)) v = 0.f;
            a0 = fmaf(v, fcw[j * 2 + 0], a0);
            a1 = fmaf(v, fcw[j * 2 + 1], a1);
        }
        float* s0 = (float*)sPart;
        float* s1 = (float*)sPart + 256;
        s0[tid] = a0; s1[tid] = a1;
        __syncthreads();
        for (int o = 128; o > 0; o >>= 1) {
            if (tid < o) { s0[tid] += s0[tid + o]; s1[tid] += s1[tid + o]; }
            __syncthreads();
        }
        if (tid == 0) { out[b * 2 + 0] = s0[0]; out[b * 2 + 1] = s1[0]; }
    }
}

// ---------------- launch ----------------
extern "C" void kernel_launch(void* const* d_in, const int* in_sizes, int n_in,
                              void* d_out, int out_size) {
    const float* x     = (const float*)d_in[0];
    const float* pos   = (const float*)d_in[1];
    const float* ea    = (const float*)d_in[2];
    const int*   ei    = (const int*)  d_in[3];
    const int*   batch = (const int*)  d_in[4];
    const float* fcw   = (const float*)d_in[5];
    const float* w1 = (const float*)d_in[6];
    const float* w2 = (const float*)d_in[7];
    const float* w3 = (const float*)d_in[8];
    const float* w4 = (const float*)d_in[9];
    const float* w5 = (const float*)d_in[10];
    const float* w6 = (const float*)d_in[11];
    const float* w7 = (const float*)d_in[12];

    k_mega<<<NBLK, NTHR>>>(x, pos, ea, ei, batch, fcw,
                           w1, w2, w3, w4, w5, w6, w7, (float*)d_out);
}

// round 5
// speedup vs baseline: 1.1543x; 1.1543x over previous
#include <cuda_runtime.h>
#include <math.h>

// ---------------- static problem config ----------------
#define NNODES   102400
#define NEDGES   819200
#define NBATCH   16
#define GCELLS   72
#define GXDIM    8
#define PSX      16.0f
#define PSY      12.0f
#define FC_IN    2304
#define NTILES   12800           // NNODES / 8
#define NBLK     592             // 148 SMs * 4 blocks (full co-residency)
#define NTHR     256

// ---------------- scratch (device globals; no allocation) ----------------
__device__ float    g_basis[(size_t)NEDGES * 8];   // pre-scaled by 1/deg(dst)
__device__ int      g_srcs [NEDGES];
__device__ int      g_cnt  [NNODES];
__device__ int      g_rowp [NNODES + 1];
__device__ int      g_wcur [NNODES];
__device__ float    g_invc [NNODES];
__device__ float    g_bufA [(size_t)NNODES * 32];
__device__ float    g_bufB [(size_t)NNODES * 32];
__device__ float    g_bufC [(size_t)NNODES * 32];
__device__ unsigned g_pool [NBATCH * GCELLS * 32];
__device__ int      g_bsum [128];
__device__ unsigned g_bar_gen;
__device__ unsigned g_bar_cnt;

// ---------------- packed fp32x2 helpers (sm_103a FFMA2) ----------------
typedef unsigned long long u64;
__device__ __forceinline__ u64 pack2(float lo, float hi) {
    u64 r;
    asm("mov.b64 %0, {%1,%2};" : "=l"(r)
        : "r"(__float_as_uint(lo)), "r"(__float_as_uint(hi)));
    return r;
}
__device__ __forceinline__ float2 unpack2(u64 v) {
    unsigned lo, hi;
    asm("mov.b64 {%0,%1}, %2;" : "=r"(lo), "=r"(hi) : "l"(v));
    return make_float2(__uint_as_float(lo), __uint_as_float(hi));
}
__device__ __forceinline__ u64 fma2(u64 a, u64 b, u64 c) {
    u64 d;
    asm("fma.rn.f32x2 %0, %1, %2, %3;" : "=l"(d) : "l"(a), "l"(b), "l"(c));
    return d;
}
__device__ __forceinline__ unsigned enc_f32(float f) {
    unsigned u = __float_as_uint(f);
    return (u & 0x80000000u) ? ~u : (u | 0x80000000u);
}
__device__ __forceinline__ float fast_elu(float o) {
    return (o > 0.f) ? o : (__expf(o) - 1.0f);
}

// ---------------- software grid barrier ----------------
__device__ __forceinline__ void grid_barrier(unsigned target) {
    __threadfence();
    __syncthreads();
    if (threadIdx.x == 0) {
        unsigned my = atomicAdd(&g_bar_cnt, 1u);
        if (my == NBLK - 1u) {
            g_bar_cnt = 0u;
            __threadfence();
            atomicExch(&g_bar_gen, target);
        } else {
            while (*(volatile unsigned*)&g_bar_gen < target) { __nanosleep(64); }
        }
    }
    __syncthreads();
}

// ---------------- conv1 phase (Cin=1 -> Cout=8) ----------------
__device__ void conv1_phase(const float* __restrict__ x, float* __restrict__ hout,
                            const float* __restrict__ W) {
    int tid = threadIdx.x, lane = tid & 31, w = tid >> 5;
    float wreg[8];
#pragma unroll
    for (int k = 0; k < 8; k++) wreg[k] = __ldg(&W[k * 8 + (lane & 7)]);
    for (int node = blockIdx.x * 8 + w; node < NNODES; node += NBLK * 8) {
        int beg = g_rowp[node], end = g_rowp[node + 1];
        float a[8] = {0, 0, 0, 0, 0, 0, 0, 0};
        for (int e = beg + lane; e < end; e += 32) {
            float xv = __ldg(&x[g_srcs[e]]);
            const float4* bp = (const float4*)(g_basis + (size_t)e * 8);
            float4 b0 = __ldg(bp), b1 = __ldg(bp + 1);
            a[0] = fmaf(b0.x, xv, a[0]); a[1] = fmaf(b0.y, xv, a[1]);
            a[2] = fmaf(b0.z, xv, a[2]); a[3] = fmaf(b0.w, xv, a[3]);
            a[4] = fmaf(b1.x, xv, a[4]); a[5] = fmaf(b1.y, xv, a[5]);
            a[6] = fmaf(b1.z, xv, a[6]); a[7] = fmaf(b1.w, xv, a[7]);
        }
#pragma unroll
        for (int k = 0; k < 8; k++)
#pragma unroll
            for (int off = 16; off; off >>= 1)
                a[k] += __shfl_xor_sync(0xffffffffu, a[k], off);
        if (lane < 8) {
            float o = 0.f;
#pragma unroll
            for (int k = 0; k < 8; k++) o = fmaf(a[k], wreg[k], o);
            hout[(size_t)node * 8 + lane] = fast_elu(o);
        }
    }
}

// ---------------- fused spline conv phase (Cin in {8,16,32}) ----------------
// Pairing: acc2[q] = (agg[j_lo], agg[j_lo+Cin]) so the FMA2 multiplier is two
// ADJACENT basis floats = a raw u64 half of the basis load (no pack/select).
//   Cin=32: jp = q*32+lane,           bpair = v[q]          (v = 4 u64s)
//   Cin=16: jp = (2*hi16+q)*16+ci,    bpair = hi16 ? v[2+q] : v[q]
//   Cin= 8: jp = lane,                bpair = v[qq]  (2-level select)
// smem row jp holds pairs for 8 nodes; GEMM: slice s reads rows via broadcast
// LDS.128, W pairs (W[j_lo],W[j_lo+Cin]) loaded per tile (L1-hot LDG.64),
// j_lo = (jp/Cin)*2*Cin + jp%Cin. Warp folds lo+hi before storing partials.
template <int Cin, int Cout, bool POOL>
__device__ void conv_phase(const float* __restrict__ hin, float* __restrict__ hout,
                           const float* __restrict__ resid, const float* __restrict__ W,
                           const float* __restrict__ pos, const int* __restrict__ batch,
                           u64* sA2, float* sPart) {
    constexpr int KC  = 8 * Cin;
    constexpr int RP  = KC / 64;            // u64 accs per lane: 1,2,4
    constexpr int JPH = KC / 2;             // pair rows: 32,64,128
    constexpr int SLC = (Cout == 32) ? 8 : 16;
    constexpr int JP2 = JPH / SLC;          // pair rows per slice: 2,4,8,16
    constexpr int PAD = 10;                 // u64 row stride

    int tid = threadIdx.x, lane = tid & 31, w = tid >> 5;
    int ci  = lane & (Cin - 1);
    int hi16 = lane >> 4;
    int qq  = (lane >> 3) & 3;
    int co  = lane & (Cout - 1);
    int s   = (Cout == 32) ? w : (w * 2 + hi16);

    for (int tile = blockIdx.x; tile < NTILES; tile += NBLK) {
        int node = tile * 8 + w;
        int beg = g_rowp[node], end = g_rowp[node + 1];
        int deg = end - beg;

        // ---- aggregation ----
        u64 acc2[RP];
#pragma unroll
        for (int q = 0; q < RP; q++) acc2[q] = 0ull;
        int degc = deg < 32 ? deg : 32;
        int s_l = (lane < degc) ? g_srcs[beg + lane] : 0;

        for (int e0 = 0; e0 < degc; e0 += 2) {
            float xv[2]; ulonglong2 v0[2], v1[2];
#pragma unroll
            for (int u = 0; u < 2; u++) {
                int e = e0 + u;
                bool p = e < degc;
                int sidx = __shfl_sync(0xffffffffu, s_l, e & 31);
                xv[u] = p ? __ldg(&hin[(size_t)sidx * Cin + ci]) : 0.f;
                const ulonglong2* bp =
                    (const ulonglong2*)(g_basis + (size_t)(beg + (p ? e : 0)) * 8);
                v0[u] = __ldg(bp); v1[u] = __ldg(bp + 1);
            }
#pragma unroll
            for (int u = 0; u < 2; u++) {
                u64 x2 = pack2(xv[u], xv[u]);
                if (Cin == 32) {
                    acc2[0] = fma2(v0[u].x, x2, acc2[0]);
                    acc2[1] = fma2(v0[u].y, x2, acc2[1]);
                    acc2[2] = fma2(v1[u].x, x2, acc2[2]);
                    acc2[3] = fma2(v1[u].y, x2, acc2[3]);
                } else if (Cin == 16) {
                    acc2[0] = fma2(hi16 ? v1[u].x : v0[u].x, x2, acc2[0]);
                    acc2[RP - 1] = fma2(hi16 ? v1[u].y : v0[u].y, x2, acc2[RP - 1]);
                } else {            // Cin == 8
                    ulonglong2 t = (qq & 2) ? v1[u] : v0[u];
                    acc2[0] = fma2((qq & 1) ? t.y : t.x, x2, acc2[0]);
                }
            }
        }
        for (int e = 32; e < deg; e++) {          // rare high-degree tail
            int sidx = g_srcs[beg + e];
            float xv = __ldg(&hin[(size_t)sidx * Cin + ci]);
            const ulonglong2* bp = (const ulonglong2*)(g_basis + (size_t)(beg + e) * 8);
            ulonglong2 a0 = __ldg(bp), a1 = __ldg(bp + 1);
            u64 x2 = pack2(xv, xv);
            if (Cin == 32) {
                acc2[0] = fma2(a0.x, x2, acc2[0]);
                acc2[1] = fma2(a0.y, x2, acc2[1]);
                acc2[2] = fma2(a1.x, x2, acc2[2]);
                acc2[3] = fma2(a1.y, x2, acc2[3]);
            } else if (Cin == 16) {
                acc2[0] = fma2(hi16 ? a1.x : a0.x, x2, acc2[0]);
                acc2[RP - 1] = fma2(hi16 ? a1.y : a0.y, x2, acc2[RP - 1]);
            } else {
                ulonglong2 t = (qq & 2) ? a1 : a0;
                acc2[0] = fma2((qq & 1) ? t.y : t.x, x2, acc2[0]);
            }
        }
        // store pairs to smem rows
        if (Cin == 32) {
#pragma unroll
            for (int q = 0; q < RP; q++)
                sA2[(q * 32 + lane) * PAD + w] = acc2[q];
        } else if (Cin == 16) {
            sA2[((2 * hi16 + 0) * 16 + ci) * PAD + w] = acc2[0];
            sA2[((2 * hi16 + 1) * 16 + ci) * PAD + w] = acc2[RP - 1];
        } else {
            sA2[lane * PAD + w] = acc2[0];
        }
        __syncthreads();

        // ---- GEMM: slice s; W pairs per tile (L1-hot), nodes via LDS.128 ----
        u64 acc[8];
#pragma unroll
        for (int n = 0; n < 8; n++) acc[n] = 0ull;
#pragma unroll
        for (int i = 0; i < JP2; i++) {
            int jp = s * JP2 + i;
            int jlo = (jp / Cin) * (2 * Cin) + (jp % Cin);
            u64 w2 = pack2(__ldg(&W[jlo * Cout + co]),
                           __ldg(&W[(jlo + Cin) * Cout + co]));
            const u64* row = &sA2[jp * PAD];
#pragma unroll
            for (int m = 0; m < 4; m++) {
                ulonglong2 v = *(const ulonglong2*)&row[2 * m];
                acc[2 * m]     = fma2(v.x, w2, acc[2 * m]);
                acc[2 * m + 1] = fma2(v.y, w2, acc[2 * m + 1]);
            }
        }
#pragma unroll
        for (int n = 0; n < 8; n++) {
            float2 v = unpack2(acc[n]);
            sPart[(s * 8 + n) * Cout + co] = v.x + v.y;
        }
        __syncthreads();

        // ---- reduce slices + epilogue ----
        if (tid < 8 * Cout) {
            int n = tid / Cout;
            int c = tid % Cout;
            float sum = 0.f;
#pragma unroll
            for (int ss = 0; ss < SLC; ss++)
                sum += sPart[(ss * 8 + n) * Cout + c];
            int node2 = tile * 8 + n;
            float o = fast_elu(sum);                  // mean folded into basis
            if (resid) o += resid[(size_t)node2 * Cout + c];
            if (POOL) {
                float px = pos[node2 * 3 + 0], py = pos[node2 * 3 + 1];
                int cx = (int)floorf(px / PSX);
                int cy = (int)floorf(py / PSY);
                int cl = batch[node2] * GCELLS + cy * GXDIM + cx;
                atomicMax(&g_pool[cl * 32 + c], enc_f32(o));
            } else {
                hout[(size_t)node2 * Cout + c] = o;
            }
        }
        __syncthreads();
    }
}

// ---------------- the mega kernel ----------------
__global__ void __launch_bounds__(NTHR, 4)
k_mega(const float* __restrict__ x,   const float* __restrict__ pos,
       const float* __restrict__ ea,  const int* __restrict__ ei,
       const int* __restrict__ batch, const float* __restrict__ fcw,
       const float* __restrict__ w1, const float* __restrict__ w2,
       const float* __restrict__ w3, const float* __restrict__ w4,
       const float* __restrict__ w5, const float* __restrict__ w6,
       const float* __restrict__ w7, float* __restrict__ out) {
    __shared__ __align__(16) u64   sA2[128 * 10];   // 10.2 KB
    __shared__ __align__(16) float sPart[2048];     // 8 KB
    __shared__ int sScan[256];

    const int tid = threadIdx.x;
    const int gtid = blockIdx.x * NTHR + tid;
    const int* src = ei;
    const int* dst = ei + NEDGES;
    unsigned barbase = *(volatile unsigned*)&g_bar_gen;
    __syncthreads();

    // ---- P0: zero counters + pool ----
    for (int i = gtid; i < NNODES; i += NBLK * NTHR) g_cnt[i] = 0;
    for (int i = gtid; i < NBATCH * GCELLS * 32; i += NBLK * NTHR)
        g_pool[i] = 0x007FFFFFu;
    grid_barrier(barbase + 1);

    // ---- P1: degree count ----
    for (int e = gtid; e < NEDGES; e += NBLK * NTHR)
        atomicAdd(&g_cnt[dst[e]], 1);
    grid_barrier(barbase + 2);

    // ---- P2a: block-local scan (blocks 0..99) ----
    if (blockIdx.x < 100) {
        int b = blockIdx.x;
        int base = b * 1024 + tid * 4;
        int v0 = g_cnt[base + 0], v1 = g_cnt[base + 1];
        int v2 = g_cnt[base + 2], v3 = g_cnt[base + 3];
        int sv = v0 + v1 + v2 + v3;
        sScan[tid] = sv;
        __syncthreads();
        for (int off = 1; off < 256; off <<= 1) {
            int t = (tid >= off) ? sScan[tid - off] : 0;
            __syncthreads();
            sScan[tid] += t;
            __syncthreads();
        }
        int excl = sScan[tid] - sv;
        g_rowp[base + 0] = excl;
        g_rowp[base + 1] = excl + v0;
        g_rowp[base + 2] = excl + v0 + v1;
        g_rowp[base + 3] = excl + v0 + v1 + v2;
        if (tid == 255) g_bsum[b] = sScan[255];
    }
    grid_barrier(barbase + 3);

    // ---- P2b: scan of 100 block sums (block 0) ----
    if (blockIdx.x == 0) {
        int v = (tid < 100) ? g_bsum[tid] : 0;
        sScan[tid] = v;
        __syncthreads();
        for (int off = 1; off < 256; off <<= 1) {
            int a = (tid >= off) ? sScan[tid - off] : 0;
            __syncthreads();
            sScan[tid] += a;
            __syncthreads();
        }
        if (tid < 100) g_bsum[tid] = sScan[tid] - v;
    }
    grid_barrier(barbase + 4);

    // ---- P2c: global row pointers + inverse counts ----
    for (int i = gtid; i < NNODES; i += NBLK * NTHR) {
        int r = g_rowp[i] + g_bsum[i >> 10];
        g_rowp[i] = r;
        g_wcur[i] = r;
        int c = g_cnt[i];
        g_invc[i] = 1.0f / (float)(c > 0 ? c : 1);
    }
    if (gtid == 0) g_rowp[NNODES] = NEDGES;
    grid_barrier(barbase + 5);

    // ---- P3: CSR fill + basis (pre-scaled by 1/deg(dst)) ----
    for (int e = gtid; e < NEDGES; e += NBLK * NTHR) {
        int d = dst[e];
        int p = atomicAdd(&g_wcur[d], 1);
        float ic = g_invc[d];
        g_srcs[p] = src[e];
        float u0 = fminf(fmaxf(ea[e * 3 + 0], 0.f), 1.f);
        float u1 = fminf(fmaxf(ea[e * 3 + 1], 0.f), 1.f);
        float u2 = fminf(fmaxf(ea[e * 3 + 2], 0.f), 1.f);
        float m0 = 1.f - u0, m1 = 1.f - u1, m2 = 1.f - u2;
        float c2m = ic * m2, c2u = ic * u2;
        float4 lo = make_float4(m0 * m1 * c2m, u0 * m1 * c2m, m0 * u1 * c2m, u0 * u1 * c2m);
        float4 hi = make_float4(m0 * m1 * c2u, u0 * m1 * c2u, m0 * u1 * c2u, u0 * u1 * c2u);
        float4* bo = (float4*)(g_basis + (size_t)p * 8);
        bo[0] = lo; bo[1] = hi;
    }
    grid_barrier(barbase + 6);

    // ---- P4..P10: seven conv layers ----
    conv1_phase(x, g_bufA, w1);
    grid_barrier(barbase + 7);
    conv_phase<8,  16, false>(g_bufA, g_bufB, nullptr, w2, pos, batch, sA2, sPart);
    grid_barrier(barbase + 8);
    conv_phase<16, 16, false>(g_bufB, g_bufA, nullptr, w3, pos, batch, sA2, sPart);
    grid_barrier(barbase + 9);
    conv_phase<16, 16, false>(g_bufA, g_bufC, g_bufB, w4, pos, batch, sA2, sPart);
    grid_barrier(barbase + 10);
    conv_phase<16, 32, false>(g_bufC, g_bufA, nullptr, w5, pos, batch, sA2, sPart);
    grid_barrier(barbase + 11);
    conv_phase<32, 32, false>(g_bufA, g_bufB, nullptr, w6, pos, batch, sA2, sPart);
    grid_barrier(barbase + 12);
    conv_phase<32, 32, true >(g_bufB, g_bufC, g_bufA, w7, pos, batch, sA2, sPart);
    grid_barrier(barbase + 13);

    // ---- P11: FC head (blocks 0..15) ----
    if (blockIdx.x < NBATCH) {
        int b = blockIdx.x;
        float a0 = 0.f, a1 = 0.f;
        for (int j = tid; j < FC_IN; j += NTHR) {
            unsigned u = g_pool[b * FC_IN + j];
            float v = (u & 0x80000000u) ? __uint_as_float(u & 0x7fffffffu)
                                        : __uint_as_float(~u);
            if (!isfinite(v)) v = 0.f;
            a0 = fmaf(v, fcw[j * 2 + 0], a0);
            a1 = fmaf(v, fcw[j * 2 + 1], a1);
        }
        float* s0 = sPart;
        float* s1 = sPart + 256;
        s0[tid] = a0; s1[tid] = a1;
        __syncthreads();
        for (int o = 128; o > 0; o >>= 1) {
            if (tid < o) { s0[tid] += s0[tid + o]; s1[tid] += s1[tid + o]; }
            __syncthreads();
        }
        if (tid == 0) { out[b * 2 + 0] = s0[0]; out[b * 2 + 1] = s1[0]; }
    }
}

// ---------------- launch ----------------
extern "C" void kernel_launch(void* const* d_in, const int* in_sizes, int n_in,
                              void* d_out, int out_size) {
    const float* x     = (const float*)d_in[0];
    const float* pos   = (const float*)d_in[1];
    const float* ea    = (const float*)d_in[2];
    const int*   ei    = (const int*)  d_in[3];
    const int*   batch = (const int*)  d_in[4];
    const float* fcw   = (const float*)d_in[5];
    const float* w1 = (const float*)d_in[6];
    const float* w2 = (const float*)d_in[7];
    const float* w3 = (const float*)d_in[8];
    const float* w4 = (const float*)d_in[9];
    const float* w5 = (const float*)d_in[10];
    const float* w6 = (const float*)d_in[11];
    const float* w7 = (const float*)d_in[12];

    k_mega<<<NBLK, NTHR>>>(x, pos, ea, ei, batch, fcw,
                           w1, w2, w3, w4, w5, w6, w7, (float*)d_out);
}

// round 6
// speedup vs baseline: 1.2519x; 1.0846x over previous
#include <cuda_runtime.h>
#include <math.h>

// ---------------- static problem config ----------------
#define NNODES   102400
#define NEDGES   819200
#define NBATCH   16
#define GCELLS   72
#define GXDIM    8
#define PSX      16.0f
#define PSY      12.0f
#define FC_IN    2304
#define NTILES   12800           // NNODES / 8
#define NBLK     592             // 148 SMs * 4 blocks (full co-residency)
#define NTHR     256

// ---------------- scratch (device globals; no allocation) ----------------
// g_cnt invariant: all-zero at kernel entry (BSS at load; restored in P2c).
__device__ float    g_basis[(size_t)NEDGES * 8];   // pre-scaled by 1/deg(dst)
__device__ int      g_srcs [NEDGES];
__device__ int      g_cnt  [NNODES];
__device__ int      g_rowp [NNODES + 1];
__device__ int      g_wcur [NNODES];
__device__ float    g_invc [NNODES];
__device__ float    g_bufA [(size_t)NNODES * 32];
__device__ float    g_bufB [(size_t)NNODES * 32];
__device__ float    g_bufC [(size_t)NNODES * 32];
__device__ unsigned g_pool [NBATCH * GCELLS * 32];
__device__ int      g_bsum [128];
__device__ unsigned g_bar_gen;
__device__ unsigned g_bar_cnt;

// ---------------- packed fp32x2 helpers (sm_103a FFMA2) ----------------
typedef unsigned long long u64;
__device__ __forceinline__ u64 pack2(float lo, float hi) {
    u64 r;
    asm("mov.b64 %0, {%1,%2};" : "=l"(r)
        : "r"(__float_as_uint(lo)), "r"(__float_as_uint(hi)));
    return r;
}
__device__ __forceinline__ float2 unpack2(u64 v) {
    unsigned lo, hi;
    asm("mov.b64 {%0,%1}, %2;" : "=r"(lo), "=r"(hi) : "l"(v));
    return make_float2(__uint_as_float(lo), __uint_as_float(hi));
}
__device__ __forceinline__ u64 fma2(u64 a, u64 b, u64 c) {
    u64 d;
    asm("fma.rn.f32x2 %0, %1, %2, %3;" : "=l"(d) : "l"(a), "l"(b), "l"(c));
    return d;
}
__device__ __forceinline__ unsigned enc_f32(float f) {
    unsigned u = __float_as_uint(f);
    return (u & 0x80000000u) ? ~u : (u | 0x80000000u);
}
__device__ __forceinline__ float fast_elu(float o) {
    return (o > 0.f) ? o : (__expf(o) - 1.0f);
}

// ---------------- software grid barrier ----------------
__device__ __forceinline__ void grid_barrier(unsigned target) {
    __threadfence();
    __syncthreads();
    if (threadIdx.x == 0) {
        unsigned my = atomicAdd(&g_bar_cnt, 1u);
        if (my == NBLK - 1u) {
            g_bar_cnt = 0u;
            __threadfence();
            atomicExch(&g_bar_gen, target);
        } else {
            while (*(volatile unsigned*)&g_bar_gen < target) { __nanosleep(64); }
        }
    }
    __syncthreads();
}

// ---------------- conv1 phase (Cin=1 -> Cout=8) ----------------
__device__ void conv1_phase(const float* __restrict__ x, float* __restrict__ hout,
                            const float* __restrict__ W) {
    int tid = threadIdx.x, lane = tid & 31, w = tid >> 5;
    float wreg[8];
#pragma unroll
    for (int k = 0; k < 8; k++) wreg[k] = __ldg(&W[k * 8 + (lane & 7)]);
    for (int node = blockIdx.x * 8 + w; node < NNODES; node += NBLK * 8) {
        int beg = g_rowp[node], end = g_rowp[node + 1];
        float a[8] = {0, 0, 0, 0, 0, 0, 0, 0};
        for (int e = beg + lane; e < end; e += 32) {
            float xv = __ldg(&x[g_srcs[e]]);
            const float4* bp = (const float4*)(g_basis + (size_t)e * 8);
            float4 b0 = __ldg(bp), b1 = __ldg(bp + 1);
            a[0] = fmaf(b0.x, xv, a[0]); a[1] = fmaf(b0.y, xv, a[1]);
            a[2] = fmaf(b0.z, xv, a[2]); a[3] = fmaf(b0.w, xv, a[3]);
            a[4] = fmaf(b1.x, xv, a[4]); a[5] = fmaf(b1.y, xv, a[5]);
            a[6] = fmaf(b1.z, xv, a[6]); a[7] = fmaf(b1.w, xv, a[7]);
        }
#pragma unroll
        for (int k = 0; k < 8; k++)
#pragma unroll
            for (int off = 16; off; off >>= 1)
                a[k] += __shfl_xor_sync(0xffffffffu, a[k], off);
        if (lane < 8) {
            float o = 0.f;
#pragma unroll
            for (int k = 0; k < 8; k++) o = fmaf(a[k], wreg[k], o);
            hout[(size_t)node * 8 + lane] = fast_elu(o);
        }
    }
}

// ---------------- fused spline conv phase (Cin in {8,16,32}) ----------------
// Pairing: acc2[q] = (agg[j_lo], agg[j_lo+Cin]) so the FMA2 multiplier is two
// ADJACENT basis floats = a raw u64 half of the basis load (no pack/select).
// Aggregation is unrolled 4-deep: 4 independent gathers + basis loads in
// flight before consumption (MLP ~4-8) — this is the latency hider.
template <int Cin, int Cout, bool POOL>
__device__ void conv_phase(const float* __restrict__ hin, float* __restrict__ hout,
                           const float* __restrict__ resid, const float* __restrict__ W,
                           const float* __restrict__ pos, const int* __restrict__ batch,
                           u64* sA2, float* sPart) {
    constexpr int KC  = 8 * Cin;
    constexpr int RP  = KC / 64;            // u64 accs per lane: 1,2,4
    constexpr int JPH = KC / 2;             // pair rows: 32,64,128
    constexpr int SLC = (Cout == 32) ? 8 : 16;
    constexpr int JP2 = JPH / SLC;          // pair rows per slice
    constexpr int PAD = 10;                 // u64 row stride

    int tid = threadIdx.x, lane = tid & 31, w = tid >> 5;
    int ci  = lane & (Cin - 1);
    int hi16 = lane >> 4;
    int qq  = (lane >> 3) & 3;
    int co  = lane & (Cout - 1);
    int s   = (Cout == 32) ? w : (w * 2 + hi16);

    for (int tile = blockIdx.x; tile < NTILES; tile += NBLK) {
        int node = tile * 8 + w;
        int beg = g_rowp[node], end = g_rowp[node + 1];
        int deg = end - beg;

        // ---- aggregation ----
        u64 acc2[RP];
#pragma unroll
        for (int q = 0; q < RP; q++) acc2[q] = 0ull;
        int degc = deg < 32 ? deg : 32;
        int s_l = (lane < degc) ? g_srcs[beg + lane] : 0;

#pragma unroll 1
        for (int e0 = 0; e0 < degc; e0 += 4) {
            float xv[4]; ulonglong2 v0[4], v1[4];
#pragma unroll
            for (int u = 0; u < 4; u++) {
                int e = e0 + u;
                bool p = e < degc;
                int sidx = __shfl_sync(0xffffffffu, s_l, e & 31);
                xv[u] = p ? __ldg(&hin[(size_t)sidx * Cin + ci]) : 0.f;
                const ulonglong2* bp =
                    (const ulonglong2*)(g_basis + (size_t)(beg + (p ? e : 0)) * 8);
                v0[u] = __ldg(bp); v1[u] = __ldg(bp + 1);
            }
#pragma unroll
            for (int u = 0; u < 4; u++) {
                u64 x2 = pack2(xv[u], xv[u]);
                if (Cin == 32) {
                    acc2[0] = fma2(v0[u].x, x2, acc2[0]);
                    acc2[1] = fma2(v0[u].y, x2, acc2[1]);
                    acc2[2] = fma2(v1[u].x, x2, acc2[2]);
                    acc2[3] = fma2(v1[u].y, x2, acc2[3]);
                } else if (Cin == 16) {
                    acc2[0] = fma2(hi16 ? v1[u].x : v0[u].x, x2, acc2[0]);
                    acc2[RP - 1] = fma2(hi16 ? v1[u].y : v0[u].y, x2, acc2[RP - 1]);
                } else {            // Cin == 8
                    ulonglong2 t = (qq & 2) ? v1[u] : v0[u];
                    acc2[0] = fma2((qq & 1) ? t.y : t.x, x2, acc2[0]);
                }
            }
        }
        for (int e = 32; e < deg; e++) {          // rare high-degree tail
            int sidx = g_srcs[beg + e];
            float xv = __ldg(&hin[(size_t)sidx * Cin + ci]);
            const ulonglong2* bp = (const ulonglong2*)(g_basis + (size_t)(beg + e) * 8);
            ulonglong2 a0 = __ldg(bp), a1 = __ldg(bp + 1);
            u64 x2 = pack2(xv, xv);
            if (Cin == 32) {
                acc2[0] = fma2(a0.x, x2, acc2[0]);
                acc2[1] = fma2(a0.y, x2, acc2[1]);
                acc2[2] = fma2(a1.x, x2, acc2[2]);
                acc2[3] = fma2(a1.y, x2, acc2[3]);
            } else if (Cin == 16) {
                acc2[0] = fma2(hi16 ? a1.x : a0.x, x2, acc2[0]);
                acc2[RP - 1] = fma2(hi16 ? a1.y : a0.y, x2, acc2[RP - 1]);
            } else {
                ulonglong2 t = (qq & 2) ? a1 : a0;
                acc2[0] = fma2((qq & 1) ? t.y : t.x, x2, acc2[0]);
            }
        }
        // store pairs to smem rows
        if (Cin == 32) {
#pragma unroll
            for (int q = 0; q < RP; q++)
                sA2[(q * 32 + lane) * PAD + w] = acc2[q];
        } else if (Cin == 16) {
            sA2[((2 * hi16 + 0) * 16 + ci) * PAD + w] = acc2[0];
            sA2[((2 * hi16 + 1) * 16 + ci) * PAD + w] = acc2[RP - 1];
        } else {
            sA2[lane * PAD + w] = acc2[0];
        }
        __syncthreads();

        // ---- GEMM: slice s; W pairs per tile (L1-hot), nodes via LDS.128 ----
        u64 acc[8];
#pragma unroll
        for (int n = 0; n < 8; n++) acc[n] = 0ull;
#pragma unroll
        for (int i = 0; i < JP2; i++) {
            int jp = s * JP2 + i;
            int jlo = (jp / Cin) * (2 * Cin) + (jp % Cin);
            u64 w2 = pack2(__ldg(&W[jlo * Cout + co]),
                           __ldg(&W[(jlo + Cin) * Cout + co]));
            const u64* row = &sA2[jp * PAD];
#pragma unroll
            for (int m = 0; m < 4; m++) {
                ulonglong2 v = *(const ulonglong2*)&row[2 * m];
                acc[2 * m]     = fma2(v.x, w2, acc[2 * m]);
                acc[2 * m + 1] = fma2(v.y, w2, acc[2 * m + 1]);
            }
        }
#pragma unroll
        for (int n = 0; n < 8; n++) {
            float2 v = unpack2(acc[n]);
            sPart[(s * 8 + n) * Cout + co] = v.x + v.y;
        }
        __syncthreads();

        // ---- reduce slices + epilogue ----
        if (tid < 8 * Cout) {
            int n = tid / Cout;
            int c = tid % Cout;
            float sum = 0.f;
#pragma unroll
            for (int ss = 0; ss < SLC; ss++)
                sum += sPart[(ss * 8 + n) * Cout + c];
            int node2 = tile * 8 + n;
            float o = fast_elu(sum);                  // mean folded into basis
            if (resid) o += resid[(size_t)node2 * Cout + c];
            if (POOL) {
                float px = pos[node2 * 3 + 0], py = pos[node2 * 3 + 1];
                int cx = (int)floorf(px / PSX);
                int cy = (int)floorf(py / PSY);
                int cl = batch[node2] * GCELLS + cy * GXDIM + cx;
                atomicMax(&g_pool[cl * 32 + c], enc_f32(o));
            } else {
                hout[(size_t)node2 * Cout + c] = o;
            }
        }
        __syncthreads();
    }
}

// ---------------- the mega kernel ----------------
__global__ void __launch_bounds__(NTHR, 4)
k_mega(const float* __restrict__ x,   const float* __restrict__ pos,
       const float* __restrict__ ea,  const int* __restrict__ ei,
       const int* __restrict__ batch, const float* __restrict__ fcw,
       const float* __restrict__ w1, const float* __restrict__ w2,
       const float* __restrict__ w3, const float* __restrict__ w4,
       const float* __restrict__ w5, const float* __restrict__ w6,
       const float* __restrict__ w7, float* __restrict__ out) {
    __shared__ __align__(16) u64   sA2[128 * 10];   // 10.2 KB
    __shared__ __align__(16) float sPart[2048];     // 8 KB
    __shared__ int sScan[256];

    const int tid = threadIdx.x;
    const int gtid = blockIdx.x * NTHR + tid;
    const int* src = ei;
    const int* dst = ei + NEDGES;
    unsigned barbase = *(volatile unsigned*)&g_bar_gen;
    __syncthreads();

    // ---- P1: degree count (g_cnt is all-zero on entry) + pool init ----
    for (int i = gtid; i < NBATCH * GCELLS * 32; i += NBLK * NTHR)
        g_pool[i] = 0x007FFFFFu;                     // enc(-inf)
    for (int e = gtid; e < NEDGES; e += NBLK * NTHR)
        atomicAdd(&g_cnt[dst[e]], 1);
    grid_barrier(barbase + 1);

    // ---- P2a: block-local scan (blocks 0..99) ----
    if (blockIdx.x < 100) {
        int b = blockIdx.x;
        int base = b * 1024 + tid * 4;
        int v0 = g_cnt[base + 0], v1 = g_cnt[base + 1];
        int v2 = g_cnt[base + 2], v3 = g_cnt[base + 3];
        int sv = v0 + v1 + v2 + v3;
        sScan[tid] = sv;
        __syncthreads();
        for (int off = 1; off < 256; off <<= 1) {
            int t = (tid >= off) ? sScan[tid - off] : 0;
            __syncthreads();
            sScan[tid] += t;
            __syncthreads();
        }
        int excl = sScan[tid] - sv;
        g_rowp[base + 0] = excl;
        g_rowp[base + 1] = excl + v0;
        g_rowp[base + 2] = excl + v0 + v1;
        g_rowp[base + 3] = excl + v0 + v1 + v2;
        if (tid == 255) g_bsum[b] = sScan[255];
    }
    grid_barrier(barbase + 2);

    // ---- P2b: scan of 100 block sums (block 0) ----
    if (blockIdx.x == 0) {
        int v = (tid < 100) ? g_bsum[tid] : 0;
        sScan[tid] = v;
        __syncthreads();
        for (int off = 1; off < 256; off <<= 1) {
            int a = (tid >= off) ? sScan[tid - off] : 0;
            __syncthreads();
            sScan[tid] += a;
            __syncthreads();
        }
        if (tid < 100) g_bsum[tid] = sScan[tid] - v;
    }
    grid_barrier(barbase + 3);

    // ---- P2c: global row pointers + inverse counts; restore g_cnt = 0 ----
    for (int i = gtid; i < NNODES; i += NBLK * NTHR) {
        int r = g_rowp[i] + g_bsum[i >> 10];
        g_rowp[i] = r;
        g_wcur[i] = r;
        int c = g_cnt[i];
        g_cnt[i] = 0;                               // invariant for next run
        g_invc[i] = 1.0f / (float)(c > 0 ? c : 1);
    }
    if (gtid == 0) g_rowp[NNODES] = NEDGES;
    grid_barrier(barbase + 4);

    // ---- P3: CSR fill + basis (pre-scaled by 1/deg(dst)) ----
    for (int e = gtid; e < NEDGES; e += NBLK * NTHR) {
        int d = dst[e];
        int p = atomicAdd(&g_wcur[d], 1);
        float ic = g_invc[d];
        g_srcs[p] = src[e];
        float u0 = fminf(fmaxf(ea[e * 3 + 0], 0.f), 1.f);
        float u1 = fminf(fmaxf(ea[e * 3 + 1], 0.f), 1.f);
        float u2 = fminf(fmaxf(ea[e * 3 + 2], 0.f), 1.f);
        float m0 = 1.f - u0, m1 = 1.f - u1, m2 = 1.f - u2;
        float c2m = ic * m2, c2u = ic * u2;
        float4 lo = make_float4(m0 * m1 * c2m, u0 * m1 * c2m, m0 * u1 * c2m, u0 * u1 * c2m);
        float4 hi = make_float4(m0 * m1 * c2u, u0 * m1 * c2u, m0 * u1 * c2u, u0 * u1 * c2u);
        float4* bo = (float4*)(g_basis + (size_t)p * 8);
        bo[0] = lo; bo[1] = hi;
    }
    grid_barrier(barbase + 5);

    // ---- P4..P10: seven conv layers ----
    conv1_phase(x, g_bufA, w1);
    grid_barrier(barbase + 6);
    conv_phase<8,  16, false>(g_bufA, g_bufB, nullptr, w2, pos, batch, sA2, sPart);
    grid_barrier(barbase + 7);
    conv_phase<16, 16, false>(g_bufB, g_bufA, nullptr, w3, pos, batch, sA2, sPart);
    grid_barrier(barbase + 8);
    conv_phase<16, 16, false>(g_bufA, g_bufC, g_bufB, w4, pos, batch, sA2, sPart);
    grid_barrier(barbase + 9);
    conv_phase<16, 32, false>(g_bufC, g_bufA, nullptr, w5, pos, batch, sA2, sPart);
    grid_barrier(barbase + 10);
    conv_phase<32, 32, false>(g_bufA, g_bufB, nullptr, w6, pos, batch, sA2, sPart);
    grid_barrier(barbase + 11);
    conv_phase<32, 32, true >(g_bufB, g_bufC, g_bufA, w7, pos, batch, sA2, sPart);
    grid_barrier(barbase + 12);

    // ---- P11: FC head (blocks 0..15) ----
    if (blockIdx.x < NBATCH) {
        int b = blockIdx.x;
        float a0 = 0.f, a1 = 0.f;
        for (int j = tid; j < FC_IN; j += NTHR) {
            unsigned u = g_pool[b * FC_IN + j];
            float v = (u & 0x80000000u) ? __uint_as_float(u & 0x7fffffffu)
                                        : __uint_as_float(~u);
            if (!isfinite(v)) v = 0.f;
            a0 = fmaf(v, fcw[j * 2 + 0], a0);
            a1 = fmaf(v, fcw[j * 2 + 1], a1);
        }
        float* s0 = sPart;
        float* s1 = sPart + 256;
        s0[tid] = a0; s1[tid] = a1;
        __syncthreads();
        for (int o = 128; o > 0; o >>= 1) {
            if (tid < o) { s0[tid] += s0[tid + o]; s1[tid] += s1[tid + o]; }
            __syncthreads();
        }
        if (tid == 0) { out[b * 2 + 0] = s0[0]; out[b * 2 + 1] = s1[0]; }
    }
}

// ---------------- launch ----------------
extern "C" void kernel_launch(void* const* d_in, const int* in_sizes, int n_in,
                              void* d_out, int out_size) {
    const float* x     = (const float*)d_in[0];
    const float* pos   = (const float*)d_in[1];
    const float* ea    = (const float*)d_in[2];
    const int*   ei    = (const int*)  d_in[3];
    const int*   batch = (const int*)  d_in[4];
    const float* fcw   = (const float*)d_in[5];
    const float* w1 = (const float*)d_in[6];
    const float* w2 = (const float*)d_in[7];
    const float* w3 = (const float*)d_in[8];
    const float* w4 = (const float*)d_in[9];
    const float* w5 = (const float*)d_in[10];
    const float* w6 = (const float*)d_in[11];
    const float* w7 = (const float*)d_in[12];

    k_mega<<<NBLK, NTHR>>>(x, pos, ea, ei, batch, fcw,
                           w1, w2, w3, w4, w5, w6, w7, (float*)d_out);
}

// round 7
// speedup vs baseline: 1.4011x; 1.1191x over previous
#include <cuda_runtime.h>
#include <math.h>

// ---------------- static problem config ----------------
#define NNODES   102400
#define NEDGES   819200
#define NBATCH   16
#define GCELLS   72
#define GXDIM    8
#define PSX      16.0f
#define PSY      12.0f
#define FC_IN    2304
#define NTILES2  6400            // NNODES / 16 (double tiles)
#define NBLK     592             // 148 SMs * 4 blocks (full co-residency)
#define NTHR     256

// ---------------- scratch (device globals; no allocation) ----------------
// g_cnt invariant: all-zero at kernel entry (BSS at load; restored in P2c).
__device__ float    g_basis[(size_t)NEDGES * 8];   // pre-scaled by 1/deg(dst)
__device__ int      g_srcs [NEDGES];
__device__ int      g_cnt  [NNODES];
__device__ int      g_rowp [NNODES + 1];
__device__ int      g_wcur [NNODES];
__device__ float    g_invc [NNODES];
__device__ float    g_bufA [(size_t)NNODES * 32];
__device__ float    g_bufB [(size_t)NNODES * 32];
__device__ float    g_bufC [(size_t)NNODES * 32];
__device__ unsigned g_pool [NBATCH * GCELLS * 32];
__device__ int      g_bsum [128];
__device__ unsigned g_bar_gen;
__device__ unsigned g_bar_cnt;

// ---------------- packed fp32x2 helpers (sm_103a FFMA2) ----------------
typedef unsigned long long u64;
__device__ __forceinline__ u64 pack2(float lo, float hi) {
    u64 r;
    asm("mov.b64 %0, {%1,%2};" : "=l"(r)
        : "r"(__float_as_uint(lo)), "r"(__float_as_uint(hi)));
    return r;
}
__device__ __forceinline__ float2 unpack2(u64 v) {
    unsigned lo, hi;
    asm("mov.b64 {%0,%1}, %2;" : "=r"(lo), "=r"(hi) : "l"(v));
    return make_float2(__uint_as_float(lo), __uint_as_float(hi));
}
__device__ __forceinline__ u64 fma2(u64 a, u64 b, u64 c) {
    u64 d;
    asm("fma.rn.f32x2 %0, %1, %2, %3;" : "=l"(d) : "l"(a), "l"(b), "l"(c));
    return d;
}
__device__ __forceinline__ unsigned enc_f32(float f) {
    unsigned u = __float_as_uint(f);
    return (u & 0x80000000u) ? ~u : (u | 0x80000000u);
}
__device__ __forceinline__ float fast_elu(float o) {
    return (o > 0.f) ? o : (__expf(o) - 1.0f);
}

// ---------------- software grid barrier ----------------
__device__ __forceinline__ void grid_barrier(unsigned target) {
    __threadfence();
    __syncthreads();
    if (threadIdx.x == 0) {
        unsigned my = atomicAdd(&g_bar_cnt, 1u);
        if (my == NBLK - 1u) {
            g_bar_cnt = 0u;
            __threadfence();
            atomicExch(&g_bar_gen, target);
        } else {
            while (*(volatile unsigned*)&g_bar_gen < target) { __nanosleep(64); }
        }
    }
    __syncthreads();
}

// ---------------- conv1 phase (Cin=1 -> Cout=8) ----------------
__device__ void conv1_phase(const float* __restrict__ x, float* __restrict__ hout,
                            const float* __restrict__ W) {
    int tid = threadIdx.x, lane = tid & 31, w = tid >> 5;
    float wreg[8];
#pragma unroll
    for (int k = 0; k < 8; k++) wreg[k] = __ldg(&W[k * 8 + (lane & 7)]);
    for (int node = blockIdx.x * 8 + w; node < NNODES; node += NBLK * 8) {
        int beg = g_rowp[node], end = g_rowp[node + 1];
        float a[8] = {0, 0, 0, 0, 0, 0, 0, 0};
        for (int e = beg + lane; e < end; e += 32) {
            float xv = __ldg(&x[g_srcs[e]]);
            const float4* bp = (const float4*)(g_basis + (size_t)e * 8);
            float4 b0 = __ldg(bp), b1 = __ldg(bp + 1);
            a[0] = fmaf(b0.x, xv, a[0]); a[1] = fmaf(b0.y, xv, a[1]);
            a[2] = fmaf(b0.z, xv, a[2]); a[3] = fmaf(b0.w, xv, a[3]);
            a[4] = fmaf(b1.x, xv, a[4]); a[5] = fmaf(b1.y, xv, a[5]);
            a[6] = fmaf(b1.z, xv, a[6]); a[7] = fmaf(b1.w, xv, a[7]);
        }
#pragma unroll
        for (int k = 0; k < 8; k++)
#pragma unroll
            for (int off = 16; off; off >>= 1)
                a[k] += __shfl_xor_sync(0xffffffffu, a[k], off);
        if (lane < 8) {
            float o = 0.f;
#pragma unroll
            for (int k = 0; k < 8; k++) o = fmaf(a[k], wreg[k], o);
            hout[(size_t)node * 8 + lane] = fast_elu(o);
        }
    }
}

// ---------------- fused spline conv phase (Cin in {8,16,32}) ----------------
// Double tile = 16 nodes. Each warp aggregates 2 nodes (t=0,1) into
// sA2[jp][node16]; pairing acc2[q] = (agg[j_lo], agg[j_lo+Cin]) so FMA2
// multipliers are raw basis u64 halves. For Cin=16/8 only the needed basis
// half is loaded (LDG.128/LDG.64). GEMM: slice s owns JP2 jp-rows; per i one
// W pair (2 LDG) amortized over 16 nodes (8 broadcast LDS.128, 16 FMA2).
template <int Cin, int Cout, bool POOL>
__device__ void conv_phase(const float* __restrict__ hin, float* __restrict__ hout,
                           const float* __restrict__ resid, const float* __restrict__ W,
                           const float* __restrict__ pos, const int* __restrict__ batch,
                           u64* sA2, float* sPart) {
    constexpr int KC  = 8 * Cin;
    constexpr int RP  = KC / 64;            // u64 accs per lane: 1,2,4
    constexpr int JPH = KC / 2;             // pair rows: 32,64,128
    constexpr int SLC = (Cout == 32) ? 8 : 16;
    constexpr int JP2 = JPH / SLC;          // pair rows per slice
    constexpr int PADT = 18;                // u64 row stride (16 nodes + pad)

    int tid = threadIdx.x, lane = tid & 31, w = tid >> 5;
    int ci  = lane & (Cin - 1);
    int hi16 = lane >> 4;
    int qq  = (lane >> 3) & 3;
    int co  = lane & (Cout - 1);
    int s   = (Cout == 32) ? w : (w * 2 + hi16);

    for (int tile2 = blockIdx.x; tile2 < NTILES2; tile2 += NBLK) {
#pragma unroll 1
        for (int t = 0; t < 2; t++) {
            int node = tile2 * 16 + t * 8 + w;
            int beg = g_rowp[node], end = g_rowp[node + 1];
            int deg = end - beg;

            u64 acc2[RP];
#pragma unroll
            for (int q = 0; q < RP; q++) acc2[q] = 0ull;
            int degc = deg < 32 ? deg : 32;
            int s_l = (lane < degc) ? g_srcs[beg + lane] : 0;

#pragma unroll 1
            for (int e0 = 0; e0 < degc; e0 += 4) {
                float xv[4]; ulonglong2 v0[4], v1[4]; u64 bv[4];
#pragma unroll
                for (int u = 0; u < 4; u++) {
                    int e = e0 + u;
                    bool p = e < degc;
                    int sidx = __shfl_sync(0xffffffffu, s_l, e & 31);
                    xv[u] = p ? __ldg(&hin[(size_t)sidx * Cin + ci]) : 0.f;
                    const float* bbase = g_basis + (size_t)(beg + (p ? e : 0)) * 8;
                    if (Cin == 32) {
                        const ulonglong2* bp = (const ulonglong2*)bbase;
                        v0[u] = __ldg(bp); v1[u] = __ldg(bp + 1);
                    } else if (Cin == 16) {
                        v0[u] = __ldg((const ulonglong2*)bbase + hi16);
                    } else {
                        bv[u] = __ldg((const u64*)bbase + qq);
                    }
                }
#pragma unroll
                for (int u = 0; u < 4; u++) {
                    u64 x2 = pack2(xv[u], xv[u]);
                    if (Cin == 32) {
                        acc2[0] = fma2(v0[u].x, x2, acc2[0]);
                        acc2[1] = fma2(v0[u].y, x2, acc2[1]);
                        acc2[2] = fma2(v1[u].x, x2, acc2[2]);
                        acc2[3] = fma2(v1[u].y, x2, acc2[3]);
                    } else if (Cin == 16) {
                        acc2[0] = fma2(v0[u].x, x2, acc2[0]);
                        acc2[RP - 1] = fma2(v0[u].y, x2, acc2[RP - 1]);
                    } else {
                        acc2[0] = fma2(bv[u], x2, acc2[0]);
                    }
                }
            }
            for (int e = 32; e < deg; e++) {      // rare high-degree tail
                int sidx = g_srcs[beg + e];
                float xv = __ldg(&hin[(size_t)sidx * Cin + ci]);
                const float* bbase = g_basis + (size_t)(beg + e) * 8;
                u64 x2 = pack2(xv, xv);
                if (Cin == 32) {
                    const ulonglong2* bp = (const ulonglong2*)bbase;
                    ulonglong2 a0 = __ldg(bp), a1 = __ldg(bp + 1);
                    acc2[0] = fma2(a0.x, x2, acc2[0]);
                    acc2[1] = fma2(a0.y, x2, acc2[1]);
                    acc2[2] = fma2(a1.x, x2, acc2[2]);
                    acc2[3] = fma2(a1.y, x2, acc2[3]);
                } else if (Cin == 16) {
                    ulonglong2 a0 = __ldg((const ulonglong2*)bbase + hi16);
                    acc2[0] = fma2(a0.x, x2, acc2[0]);
                    acc2[RP - 1] = fma2(a0.y, x2, acc2[RP - 1]);
                } else {
                    u64 b = __ldg((const u64*)bbase + qq);
                    acc2[0] = fma2(b, x2, acc2[0]);
                }
            }
            // store pairs to smem rows (node column = t*8 + w)
            int ncol = t * 8 + w;
            if (Cin == 32) {
#pragma unroll
                for (int q = 0; q < RP; q++)
                    sA2[(q * 32 + lane) * PADT + ncol] = acc2[q];
            } else if (Cin == 16) {
                sA2[((2 * hi16 + 0) * 16 + ci) * PADT + ncol] = acc2[0];
                sA2[((2 * hi16 + 1) * 16 + ci) * PADT + ncol] = acc2[RP - 1];
            } else {
                sA2[lane * PADT + ncol] = acc2[0];
            }
        }
        __syncthreads();

        // ---- GEMM: slice s, W pair per i amortized over 16 nodes ----
        u64 acc[16];
#pragma unroll
        for (int n = 0; n < 16; n++) acc[n] = 0ull;
#pragma unroll
        for (int i = 0; i < JP2; i++) {
            int jp = s * JP2 + i;
            int jlo = (jp / Cin) * (2 * Cin) + (jp % Cin);
            u64 w2 = pack2(__ldg(&W[jlo * Cout + co]),
                           __ldg(&W[(jlo + Cin) * Cout + co]));
            const u64* row = &sA2[jp * PADT];
#pragma unroll
            for (int m = 0; m < 8; m++) {
                ulonglong2 v = *(const ulonglong2*)&row[2 * m];
                acc[2 * m]     = fma2(v.x, w2, acc[2 * m]);
                acc[2 * m + 1] = fma2(v.y, w2, acc[2 * m + 1]);
            }
        }
#pragma unroll
        for (int n = 0; n < 16; n++) {
            float2 v = unpack2(acc[n]);
            sPart[(s * 16 + n) * Cout + co] = v.x + v.y;
        }
        __syncthreads();

        // ---- reduce slices + epilogue (16 nodes) ----
#pragma unroll
        for (int rr = 0; rr < (16 * Cout + NTHR - 1) / NTHR; rr++) {
            int o = rr * NTHR + tid;
            if (o < 16 * Cout) {
                int n16 = o / Cout;
                int c   = o % Cout;
                float sum = 0.f;
#pragma unroll
                for (int ss = 0; ss < SLC; ss++)
                    sum += sPart[(ss * 16 + n16) * Cout + c];
                int node2 = tile2 * 16 + n16;
                float ov = fast_elu(sum);             // mean folded into basis
                if (resid) ov += resid[(size_t)node2 * Cout + c];
                if (POOL) {
                    float px = pos[node2 * 3 + 0], py = pos[node2 * 3 + 1];
                    int cx = (int)floorf(px / PSX);
                    int cy = (int)floorf(py / PSY);
                    int cl = batch[node2] * GCELLS + cy * GXDIM + cx;
                    atomicMax(&g_pool[cl * 32 + c], enc_f32(ov));
                } else {
                    hout[(size_t)node2 * Cout + c] = ov;
                }
            }
        }
        __syncthreads();
    }
}

// ---------------- the mega kernel ----------------
__global__ void __launch_bounds__(NTHR, 4)
k_mega(const float* __restrict__ x,   const float* __restrict__ pos,
       const float* __restrict__ ea,  const int* __restrict__ ei,
       const int* __restrict__ batch, const float* __restrict__ fcw,
       const float* __restrict__ w1, const float* __restrict__ w2,
       const float* __restrict__ w3, const float* __restrict__ w4,
       const float* __restrict__ w5, const float* __restrict__ w6,
       const float* __restrict__ w7, float* __restrict__ out) {
    __shared__ __align__(16) u64   sA2[128 * 18];   // 18 KB
    __shared__ __align__(16) float sPart[4096];     // 16 KB
    __shared__ int sScan[256];

    const int tid = threadIdx.x;
    const int gtid = blockIdx.x * NTHR + tid;
    const int* src = ei;
    const int* dst = ei + NEDGES;
    unsigned barbase = *(volatile unsigned*)&g_bar_gen;
    __syncthreads();

    // ---- P1: degree count (g_cnt all-zero on entry) + pool init ----
    for (int i = gtid; i < NBATCH * GCELLS * 32; i += NBLK * NTHR)
        g_pool[i] = 0x007FFFFFu;                     // enc(-inf)
    for (int e = gtid; e < NEDGES; e += NBLK * NTHR)
        atomicAdd(&g_cnt[dst[e]], 1);
    grid_barrier(barbase + 1);

    // ---- P2a: block-local scan (blocks 0..99) ----
    if (blockIdx.x < 100) {
        int b = blockIdx.x;
        int base = b * 1024 + tid * 4;
        int v0 = g_cnt[base + 0], v1 = g_cnt[base + 1];
        int v2 = g_cnt[base + 2], v3 = g_cnt[base + 3];
        int sv = v0 + v1 + v2 + v3;
        sScan[tid] = sv;
        __syncthreads();
        for (int off = 1; off < 256; off <<= 1) {
            int t = (tid >= off) ? sScan[tid - off] : 0;
            __syncthreads();
            sScan[tid] += t;
            __syncthreads();
        }
        int excl = sScan[tid] - sv;
        g_rowp[base + 0] = excl;
        g_rowp[base + 1] = excl + v0;
        g_rowp[base + 2] = excl + v0 + v1;
        g_rowp[base + 3] = excl + v0 + v1 + v2;
        if (tid == 255) g_bsum[b] = sScan[255];
    }
    grid_barrier(barbase + 2);

    // ---- P2b: scan of 100 block sums (block 0) ----
    if (blockIdx.x == 0) {
        int v = (tid < 100) ? g_bsum[tid] : 0;
        sScan[tid] = v;
        __syncthreads();
        for (int off = 1; off < 256; off <<= 1) {
            int a = (tid >= off) ? sScan[tid - off] : 0;
            __syncthreads();
            sScan[tid] += a;
            __syncthreads();
        }
        if (tid < 100) g_bsum[tid] = sScan[tid] - v;
    }
    grid_barrier(barbase + 3);

    // ---- P2c: global row pointers + inverse counts; restore g_cnt = 0 ----
    for (int i = gtid; i < NNODES; i += NBLK * NTHR) {
        int r = g_rowp[i] + g_bsum[i >> 10];
        g_rowp[i] = r;
        g_wcur[i] = r;
        int c = g_cnt[i];
        g_cnt[i] = 0;
        g_invc[i] = 1.0f / (float)(c > 0 ? c : 1);
    }
    if (gtid == 0) g_rowp[NNODES] = NEDGES;
    grid_barrier(barbase + 4);

    // ---- P3: CSR fill + basis (pre-scaled by 1/deg(dst)) ----
    for (int e = gtid; e < NEDGES; e += NBLK * NTHR) {
        int d = dst[e];
        int p = atomicAdd(&g_wcur[d], 1);
        float ic = g_invc[d];
        g_srcs[p] = src[e];
        float u0 = fminf(fmaxf(ea[e * 3 + 0], 0.f), 1.f);
        float u1 = fminf(fmaxf(ea[e * 3 + 1], 0.f), 1.f);
        float u2 = fminf(fmaxf(ea[e * 3 + 2], 0.f), 1.f);
        float m0 = 1.f - u0, m1 = 1.f - u1, m2 = 1.f - u2;
        float c2m = ic * m2, c2u = ic * u2;
        float4 lo = make_float4(m0 * m1 * c2m, u0 * m1 * c2m, m0 * u1 * c2m, u0 * u1 * c2m);
        float4 hi = make_float4(m0 * m1 * c2u, u0 * m1 * c2u, m0 * u1 * c2u, u0 * u1 * c2u);
        float4* bo = (float4*)(g_basis + (size_t)p * 8);
        bo[0] = lo; bo[1] = hi;
    }
    grid_barrier(barbase + 5);

    // ---- P4..P10: seven conv layers ----
    conv1_phase(x, g_bufA, w1);
    grid_barrier(barbase + 6);
    conv_phase<8,  16, false>(g_bufA, g_bufB, nullptr, w2, pos, batch, sA2, sPart);
    grid_barrier(barbase + 7);
    conv_phase<16, 16, false>(g_bufB, g_bufA, nullptr, w3, pos, batch, sA2, sPart);
    grid_barrier(barbase + 8);
    conv_phase<16, 16, false>(g_bufA, g_bufC, g_bufB, w4, pos, batch, sA2, sPart);
    grid_barrier(barbase + 9);
    conv_phase<16, 32, false>(g_bufC, g_bufA, nullptr, w5, pos, batch, sA2, sPart);
    grid_barrier(barbase + 10);
    conv_phase<32, 32, false>(g_bufA, g_bufB, nullptr, w6, pos, batch, sA2, sPart);
    grid_barrier(barbase + 11);
    conv_phase<32, 32, true >(g_bufB, g_bufC, g_bufA, w7, pos, batch, sA2, sPart);
    grid_barrier(barbase + 12);

    // ---- P11: FC head (blocks 0..15) ----
    if (blockIdx.x < NBATCH) {
        int b = blockIdx.x;
        float a0 = 0.f, a1 = 0.f;
        for (int j = tid; j < FC_IN; j += NTHR) {
            unsigned u = g_pool[b * FC_IN + j];
            float v = (u & 0x80000000u) ? __uint_as_float(u & 0x7fffffffu)
                                        : __uint_as_float(~u);
            if (!isfinite(v)) v = 0.f;
            a0 = fmaf(v, fcw[j * 2 + 0], a0);
            a1 = fmaf(v, fcw[j * 2 + 1], a1);
        }
        float* s0 = sPart;
        float* s1 = sPart + 256;
        s0[tid] = a0; s1[tid] = a1;
        __syncthreads();
        for (int o = 128; o > 0; o >>= 1) {
            if (tid < o) { s0[tid] += s0[tid + o]; s1[tid] += s1[tid + o]; }
            __syncthreads();
        }
        if (tid == 0) { out[b * 2 + 0] = s0[0]; out[b * 2 + 1] = s1[0]; }
    }
}

// ---------------- launch ----------------
extern "C" void kernel_launch(void* const* d_in, const int* in_sizes, int n_in,
                              void* d_out, int out_size) {
    const float* x     = (const float*)d_in[0];
    const float* pos   = (const float*)d_in[1];
    const float* ea    = (const float*)d_in[2];
    const int*   ei    = (const int*)  d_in[3];
    const int*   batch = (const int*)  d_in[4];
    const float* fcw   = (const float*)d_in[5];
    const float* w1 = (const float*)d_in[6];
    const float* w2 = (const float*)d_in[7];
    const float* w3 = (const float*)d_in[8];
    const float* w4 = (const float*)d_in[9];
    const float* w5 = (const float*)d_in[10];
    const float* w6 = (const float*)d_in[11];
    const float* w7 = (const float*)d_in[12];

    k_mega<<<NBLK, NTHR>>>(x, pos, ea, ei, batch, fcw,
                           w1, w2, w3, w4, w5, w6, w7, (float*)d_out);
}

// round 8
// speedup vs baseline: 1.4286x; 1.0196x over previous
#include <cuda_runtime.h>
#include <math.h>

// ---------------- static problem config ----------------
#define NNODES   102400
#define NEDGES   819200
#define NBATCH   16
#define GCELLS   72
#define GXDIM    8
#define PSX      16.0f
#define PSY      12.0f
#define FC_IN    2304
#define NTILES2  6400            // NNODES / 16 (double tiles)
#define NBLK     592             // 148 SMs * 4 blocks (full co-residency)
#define NTHR     256

// packed-W layout offsets (u64 units): layer size = (8*Cin/2)*Cout... = KC*Cout/2? no:
// size per layer = JPH * Cout u64 where JPH = 4*Cin.
#define WPK2  0        // L2: Cin=8,  Cout=16 -> 32*16  = 512
#define WPK3  512      // L3: Cin=16, Cout=16 -> 64*16  = 1024
#define WPK4  1536     // L4: same            -> 1024
#define WPK5  2560     // L5: Cin=16, Cout=32 -> 64*32  = 2048
#define WPK6  4608     // L6: Cin=32, Cout=32 -> 128*32 = 4096
#define WPK7  8704     // L7: same            -> 4096
#define WPTOT 12800

// ---------------- scratch (device globals; no allocation) ----------------
// g_cnt invariant: all-zero at kernel entry (BSS at load; restored in P2c).
__device__ float    g_basis[(size_t)NEDGES * 8];   // pre-scaled by 1/deg(dst)
__device__ int      g_srcs [NEDGES];
__device__ int      g_cnt  [NNODES];
__device__ int      g_rowp [NNODES + 1];
__device__ int      g_wcur [NNODES];
__device__ float    g_invc [NNODES];
__device__ float    g_bufA [(size_t)NNODES * 32];
__device__ float    g_bufB [(size_t)NNODES * 32];
__device__ float    g_bufC [(size_t)NNODES * 32];
__device__ unsigned g_pool [NBATCH * GCELLS * 32];
__device__ int      g_bsum [128];
__device__ unsigned long long g_wpack[WPTOT];
__device__ unsigned g_bar_gen;
__device__ unsigned g_bar_cnt;

// ---------------- packed fp32x2 helpers (sm_103a FFMA2) ----------------
typedef unsigned long long u64;
__device__ __forceinline__ u64 pack2(float lo, float hi) {
    u64 r;
    asm("mov.b64 %0, {%1,%2};" : "=l"(r)
        : "r"(__float_as_uint(lo)), "r"(__float_as_uint(hi)));
    return r;
}
__device__ __forceinline__ float2 unpack2(u64 v) {
    unsigned lo, hi;
    asm("mov.b64 {%0,%1}, %2;" : "=r"(lo), "=r"(hi) : "l"(v));
    return make_float2(__uint_as_float(lo), __uint_as_float(hi));
}
__device__ __forceinline__ u64 fma2(u64 a, u64 b, u64 c) {
    u64 d;
    asm("fma.rn.f32x2 %0, %1, %2, %3;" : "=l"(d) : "l"(a), "l"(b), "l"(c));
    return d;
}
__device__ __forceinline__ unsigned enc_f32(float f) {
    unsigned u = __float_as_uint(f);
    return (u & 0x80000000u) ? ~u : (u | 0x80000000u);
}
__device__ __forceinline__ float fast_elu(float o) {
    return (o > 0.f) ? o : (__expf(o) - 1.0f);
}

// ---------------- software grid barrier ----------------
__device__ __forceinline__ void grid_barrier(unsigned target) {
    __threadfence();
    __syncthreads();
    if (threadIdx.x == 0) {
        unsigned my = atomicAdd(&g_bar_cnt, 1u);
        if (my == NBLK - 1u) {
            g_bar_cnt = 0u;
            __threadfence();
            atomicExch(&g_bar_gen, target);
        } else {
            while (*(volatile unsigned*)&g_bar_gen < target) { __nanosleep(64); }
        }
    }
    __syncthreads();
}

// ---------------- W pack: wp[((jp>>1)*Cout+co)*2 + (jp&1)] = (W[jlo,co], W[jlo+Cin,co])
// jlo = (jp/Cin)*2*Cin + jp%Cin. Consecutive jp pairs adjacent -> GEMM LDG.128.
__device__ void pack_w(const float* __restrict__ W, u64* __restrict__ wp,
                       int Cin, int Cout, int gtid) {
    int JPH = 4 * Cin;
    int total = JPH * Cout;                 // u64 entries
    for (int m = gtid; m < total; m += NBLK * NTHR) {
        int jphalf = m / (2 * Cout);
        int rem = m % (2 * Cout);
        int co = rem >> 1;
        int jp = jphalf * 2 + (rem & 1);
        int jlo = (jp / Cin) * (2 * Cin) + (jp % Cin);
        wp[m] = pack2(W[jlo * Cout + co], W[(jlo + Cin) * Cout + co]);
    }
}

// ---------------- conv1 phase (Cin=1 -> Cout=8) ----------------
__device__ void conv1_phase(const float* __restrict__ x, float* __restrict__ hout,
                            const float* __restrict__ W) {
    int tid = threadIdx.x, lane = tid & 31, w = tid >> 5;
    float wreg[8];
#pragma unroll
    for (int k = 0; k < 8; k++) wreg[k] = __ldg(&W[k * 8 + (lane & 7)]);
    for (int node = blockIdx.x * 8 + w; node < NNODES; node += NBLK * 8) {
        int beg = g_rowp[node], end = g_rowp[node + 1];
        float a[8] = {0, 0, 0, 0, 0, 0, 0, 0};
        for (int e = beg + lane; e < end; e += 32) {
            float xv = __ldg(&x[g_srcs[e]]);
            const float4* bp = (const float4*)(g_basis + (size_t)e * 8);
            float4 b0 = __ldg(bp), b1 = __ldg(bp + 1);
            a[0] = fmaf(b0.x, xv, a[0]); a[1] = fmaf(b0.y, xv, a[1]);
            a[2] = fmaf(b0.z, xv, a[2]); a[3] = fmaf(b0.w, xv, a[3]);
            a[4] = fmaf(b1.x, xv, a[4]); a[5] = fmaf(b1.y, xv, a[5]);
            a[6] = fmaf(b1.z, xv, a[6]); a[7] = fmaf(b1.w, xv, a[7]);
        }
#pragma unroll
        for (int k = 0; k < 8; k++)
#pragma unroll
            for (int off = 16; off; off >>= 1)
                a[k] += __shfl_xor_sync(0xffffffffu, a[k], off);
        if (lane < 8) {
            float o = 0.f;
#pragma unroll
            for (int k = 0; k < 8; k++) o = fmaf(a[k], wreg[k], o);
            hout[(size_t)node * 8 + lane] = fast_elu(o);
        }
    }
}

// ---------------- fused spline conv phase (Cin in {8,16,32}) ----------------
// Double tile = 16 nodes. Each warp aggregates 2 nodes (t=0,1) into
// sA2[jp][node16]; pairing acc2[q] = (agg[j_lo], agg[j_lo+Cin]) so FMA2
// multipliers are raw basis u64 halves. For Cin=16/8 only the needed basis
// half is loaded. GEMM: slice s owns JP2 jp-rows; packed W gives TWO jp-rows
// per LDG.128, amortized over 16 nodes (16 broadcast LDS.128, 32 FMA2).
template <int Cin, int Cout, bool POOL>
__device__ void conv_phase(const float* __restrict__ hin, float* __restrict__ hout,
                           const float* __restrict__ resid, const u64* __restrict__ wp,
                           const float* __restrict__ pos, const int* __restrict__ batch,
                           u64* sA2, float* sPart) {
    constexpr int KC  = 8 * Cin;
    constexpr int RP  = KC / 64;            // u64 accs per lane: 1,2,4
    constexpr int JPH = KC / 2;             // pair rows: 32,64,128
    constexpr int SLC = (Cout == 32) ? 8 : 16;
    constexpr int JP2 = JPH / SLC;          // pair rows per slice (even: 2,4,8,16)
    constexpr int PADT = 18;                // u64 row stride (16 nodes + pad)

    int tid = threadIdx.x, lane = tid & 31, w = tid >> 5;
    int ci  = lane & (Cin - 1);
    int hi16 = lane >> 4;
    int qq  = (lane >> 3) & 3;
    int co  = lane & (Cout - 1);
    int s   = (Cout == 32) ? w : (w * 2 + hi16);

    for (int tile2 = blockIdx.x; tile2 < NTILES2; tile2 += NBLK) {
#pragma unroll 1
        for (int t = 0; t < 2; t++) {
            int node = tile2 * 16 + t * 8 + w;
            int beg = g_rowp[node], end = g_rowp[node + 1];
            int deg = end - beg;

            u64 acc2[RP];
#pragma unroll
            for (int q = 0; q < RP; q++) acc2[q] = 0ull;
            int degc = deg < 32 ? deg : 32;
            int s_l = (lane < degc) ? g_srcs[beg + lane] : 0;

#pragma unroll 1
            for (int e0 = 0; e0 < degc; e0 += 4) {
                float xv[4]; ulonglong2 v0[4], v1[4]; u64 bv[4];
#pragma unroll
                for (int u = 0; u < 4; u++) {
                    int e = e0 + u;
                    bool p = e < degc;
                    int sidx = __shfl_sync(0xffffffffu, s_l, e & 31);
                    xv[u] = p ? __ldg(&hin[(size_t)sidx * Cin + ci]) : 0.f;
                    const float* bbase = g_basis + (size_t)(beg + (p ? e : 0)) * 8;
                    if (Cin == 32) {
                        const ulonglong2* bp = (const ulonglong2*)bbase;
                        v0[u] = __ldg(bp); v1[u] = __ldg(bp + 1);
                    } else if (Cin == 16) {
                        v0[u] = __ldg((const ulonglong2*)bbase + hi16);
                    } else {
                        bv[u] = __ldg((const u64*)bbase + qq);
                    }
                }
#pragma unroll
                for (int u = 0; u < 4; u++) {
                    u64 x2 = pack2(xv[u], xv[u]);
                    if (Cin == 32) {
                        acc2[0] = fma2(v0[u].x, x2, acc2[0]);
                        acc2[1] = fma2(v0[u].y, x2, acc2[1]);
                        acc2[2] = fma2(v1[u].x, x2, acc2[2]);
                        acc2[3] = fma2(v1[u].y, x2, acc2[3]);
                    } else if (Cin == 16) {
                        acc2[0] = fma2(v0[u].x, x2, acc2[0]);
                        acc2[RP - 1] = fma2(v0[u].y, x2, acc2[RP - 1]);
                    } else {
                        acc2[0] = fma2(bv[u], x2, acc2[0]);
                    }
                }
            }
            for (int e = 32; e < deg; e++) {      // rare high-degree tail
                int sidx = g_srcs[beg + e];
                float xv = __ldg(&hin[(size_t)sidx * Cin + ci]);
                const float* bbase = g_basis + (size_t)(beg + e) * 8;
                u64 x2 = pack2(xv, xv);
                if (Cin == 32) {
                    const ulonglong2* bp = (const ulonglong2*)bbase;
                    ulonglong2 a0 = __ldg(bp), a1 = __ldg(bp + 1);
                    acc2[0] = fma2(a0.x, x2, acc2[0]);
                    acc2[1] = fma2(a0.y, x2, acc2[1]);
                    acc2[2] = fma2(a1.x, x2, acc2[2]);
                    acc2[3] = fma2(a1.y, x2, acc2[3]);
                } else if (Cin == 16) {
                    ulonglong2 a0 = __ldg((const ulonglong2*)bbase + hi16);
                    acc2[0] = fma2(a0.x, x2, acc2[0]);
                    acc2[RP - 1] = fma2(a0.y, x2, acc2[RP - 1]);
                } else {
                    u64 b = __ldg((const u64*)bbase + qq);
                    acc2[0] = fma2(b, x2, acc2[0]);
                }
            }
            // store pairs to smem rows (node column = t*8 + w)
            int ncol = t * 8 + w;
            if (Cin == 32) {
#pragma unroll
                for (int q = 0; q < RP; q++)
                    sA2[(q * 32 + lane) * PADT + ncol] = acc2[q];
            } else if (Cin == 16) {
                sA2[((2 * hi16 + 0) * 16 + ci) * PADT + ncol] = acc2[0];
                sA2[((2 * hi16 + 1) * 16 + ci) * PADT + ncol] = acc2[RP - 1];
            } else {
                sA2[lane * PADT + ncol] = acc2[0];
            }
        }
        __syncthreads();

        // ---- GEMM: slice s; one LDG.128 = packed W for TWO jp-rows ----
        u64 acc[16];
#pragma unroll
        for (int n = 0; n < 16; n++) acc[n] = 0ull;
#pragma unroll
        for (int i2 = 0; i2 < JP2 / 2; i2++) {
            int jp0 = s * JP2 + 2 * i2;          // even
            ulonglong2 wv = __ldg((const ulonglong2*)&wp[(size_t)jp0 * Cout + 2 * co]);
            const u64* row0 = &sA2[jp0 * PADT];
            const u64* row1 = &sA2[(jp0 + 1) * PADT];
#pragma unroll
            for (int m = 0; m < 8; m++) {
                ulonglong2 a0 = *(const ulonglong2*)&row0[2 * m];
                ulonglong2 a1 = *(const ulonglong2*)&row1[2 * m];
                acc[2 * m]     = fma2(a0.x, wv.x, acc[2 * m]);
                acc[2 * m + 1] = fma2(a0.y, wv.x, acc[2 * m + 1]);
                acc[2 * m]     = fma2(a1.x, wv.y, acc[2 * m]);
                acc[2 * m + 1] = fma2(a1.y, wv.y, acc[2 * m + 1]);
            }
        }
#pragma unroll
        for (int n = 0; n < 16; n++) {
            float2 v = unpack2(acc[n]);
            sPart[(s * 16 + n) * Cout + co] = v.x + v.y;
        }
        __syncthreads();

        // ---- reduce slices + epilogue (16 nodes) ----
#pragma unroll
        for (int rr = 0; rr < (16 * Cout + NTHR - 1) / NTHR; rr++) {
            int o = rr * NTHR + tid;
            if (o < 16 * Cout) {
                int n16 = o / Cout;
                int c   = o % Cout;
                float sum = 0.f;
#pragma unroll
                for (int ss = 0; ss < SLC; ss++)
                    sum += sPart[(ss * 16 + n16) * Cout + c];
                int node2 = tile2 * 16 + n16;
                float ov = fast_elu(sum);             // mean folded into basis
                if (resid) ov += resid[(size_t)node2 * Cout + c];
                if (POOL) {
                    float px = pos[node2 * 3 + 0], py = pos[node2 * 3 + 1];
                    int cx = (int)floorf(px / PSX);
                    int cy = (int)floorf(py / PSY);
                    int cl = batch[node2] * GCELLS + cy * GXDIM + cx;
                    atomicMax(&g_pool[cl * 32 + c], enc_f32(ov));
                } else {
                    hout[(size_t)node2 * Cout + c] = ov;
                }
            }
        }
        __syncthreads();
    }
}

// ---------------- the mega kernel ----------------
__global__ void __launch_bounds__(NTHR, 4)
k_mega(const float* __restrict__ x,   const float* __restrict__ pos,
       const float* __restrict__ ea,  const int* __restrict__ ei,
       const int* __restrict__ batch, const float* __restrict__ fcw,
       const float* __restrict__ w1, const float* __restrict__ w2,
       const float* __restrict__ w3, const float* __restrict__ w4,
       const float* __restrict__ w5, const float* __restrict__ w6,
       const float* __restrict__ w7, float* __restrict__ out) {
    __shared__ __align__(16) u64   sA2[128 * 18];   // 18 KB
    __shared__ __align__(16) float sPart[4096];     // 16 KB
    __shared__ int sScan[256];

    const int tid = threadIdx.x;
    const int gtid = blockIdx.x * NTHR + tid;
    const int* src = ei;
    const int* dst = ei + NEDGES;
    unsigned barbase = *(volatile unsigned*)&g_bar_gen;
    __syncthreads();

    // ---- P1: degree count + pool init + W packing ----
    for (int i = gtid; i < NBATCH * GCELLS * 32; i += NBLK * NTHR)
        g_pool[i] = 0x007FFFFFu;                     // enc(-inf)
    pack_w(w2, g_wpack + WPK2,  8, 16, gtid);
    pack_w(w3, g_wpack + WPK3, 16, 16, gtid);
    pack_w(w4, g_wpack + WPK4, 16, 16, gtid);
    pack_w(w5, g_wpack + WPK5, 16, 32, gtid);
    pack_w(w6, g_wpack + WPK6, 32, 32, gtid);
    pack_w(w7, g_wpack + WPK7, 32, 32, gtid);
    for (int e = gtid; e < NEDGES; e += NBLK * NTHR)
        atomicAdd(&g_cnt[dst[e]], 1);
    grid_barrier(barbase + 1);

    // ---- P2a: block-local scan (blocks 0..99) ----
    if (blockIdx.x < 100) {
        int b = blockIdx.x;
        int base = b * 1024 + tid * 4;
        int v0 = g_cnt[base + 0], v1 = g_cnt[base + 1];
        int v2 = g_cnt[base + 2], v3 = g_cnt[base + 3];
        int sv = v0 + v1 + v2 + v3;
        sScan[tid] = sv;
        __syncthreads();
        for (int off = 1; off < 256; off <<= 1) {
            int t = (tid >= off) ? sScan[tid - off] : 0;
            __syncthreads();
            sScan[tid] += t;
            __syncthreads();
        }
        int excl = sScan[tid] - sv;
        g_rowp[base + 0] = excl;
        g_rowp[base + 1] = excl + v0;
        g_rowp[base + 2] = excl + v0 + v1;
        g_rowp[base + 3] = excl + v0 + v1 + v2;
        if (tid == 255) g_bsum[b] = sScan[255];
    }
    grid_barrier(barbase + 2);

    // ---- P2b: scan of 100 block sums (block 0) ----
    if (blockIdx.x == 0) {
        int v = (tid < 100) ? g_bsum[tid] : 0;
        sScan[tid] = v;
        __syncthreads();
        for (int off = 1; off < 128; off <<= 1) {
            int a = (tid >= off) ? sScan[tid - off] : 0;
            __syncthreads();
            sScan[tid] += a;
            __syncthreads();
        }
        if (tid < 100) g_bsum[tid] = sScan[tid] - v;
    }
    grid_barrier(barbase + 3);

    // ---- P2c: global row pointers + inverse counts; restore g_cnt = 0 ----
    for (int i = gtid; i < NNODES; i += NBLK * NTHR) {
        int r = g_rowp[i] + g_bsum[i >> 10];
        g_rowp[i] = r;
        g_wcur[i] = r;
        int c = g_cnt[i];
        g_cnt[i] = 0;
        g_invc[i] = 1.0f / (float)(c > 0 ? c : 1);
    }
    if (gtid == 0) g_rowp[NNODES] = NEDGES;
    grid_barrier(barbase + 4);

    // ---- P3: CSR fill + basis (pre-scaled by 1/deg(dst)) ----
    for (int e = gtid; e < NEDGES; e += NBLK * NTHR) {
        int d = dst[e];
        int p = atomicAdd(&g_wcur[d], 1);
        float ic = g_invc[d];
        g_srcs[p] = src[e];
        float u0 = fminf(fmaxf(ea[e * 3 + 0], 0.f), 1.f);
        float u1 = fminf(fmaxf(ea[e * 3 + 1], 0.f), 1.f);
        float u2 = fminf(fmaxf(ea[e * 3 + 2], 0.f), 1.f);
        float m0 = 1.f - u0, m1 = 1.f - u1, m2 = 1.f - u2;
        float c2m = ic * m2, c2u = ic * u2;
        float4 lo = make_float4(m0 * m1 * c2m, u0 * m1 * c2m, m0 * u1 * c2m, u0 * u1 * c2m);
        float4 hi = make_float4(m0 * m1 * c2u, u0 * m1 * c2u, m0 * u1 * c2u, u0 * u1 * c2u);
        float4* bo = (float4*)(g_basis + (size_t)p * 8);
        bo[0] = lo; bo[1] = hi;
    }
    grid_barrier(barbase + 5);

    // ---- P4..P10: seven conv layers ----
    conv1_phase(x, g_bufA, w1);
    grid_barrier(barbase + 6);
    conv_phase<8,  16, false>(g_bufA, g_bufB, nullptr, g_wpack + WPK2, pos, batch, sA2, sPart);
    grid_barrier(barbase + 7);
    conv_phase<16, 16, false>(g_bufB, g_bufA, nullptr, g_wpack + WPK3, pos, batch, sA2, sPart);
    grid_barrier(barbase + 8);
    conv_phase<16, 16, false>(g_bufA, g_bufC, g_bufB,  g_wpack + WPK4, pos, batch, sA2, sPart);
    grid_barrier(barbase + 9);
    conv_phase<16, 32, false>(g_bufC, g_bufA, nullptr, g_wpack + WPK5, pos, batch, sA2, sPart);
    grid_barrier(barbase + 10);
    conv_phase<32, 32, false>(g_bufA, g_bufB, nullptr, g_wpack + WPK6, pos, batch, sA2, sPart);
    grid_barrier(barbase + 11);
    conv_phase<32, 32, true >(g_bufB, g_bufC, g_bufA,  g_wpack + WPK7, pos, batch, sA2, sPart);
    grid_barrier(barbase + 12);

    // ---- P11: FC head (blocks 0..15) ----
    if (blockIdx.x < NBATCH) {
        int b = blockIdx.x;
        float a0 = 0.f, a1 = 0.f;
        for (int j = tid; j < FC_IN; j += NTHR) {
            unsigned u = g_pool[b * FC_IN + j];
            float v = (u & 0x80000000u) ? __uint_as_float(u & 0x7fffffffu)
                                        : __uint_as_float(~u);
            if (!isfinite(v)) v = 0.f;
            a0 = fmaf(v, fcw[j * 2 + 0], a0);
            a1 = fmaf(v, fcw[j * 2 + 1], a1);
        }
        float* s0 = sPart;
        float* s1 = sPart + 256;
        s0[tid] = a0; s1[tid] = a1;
        __syncthreads();
        for (int o = 128; o > 0; o >>= 1) {
            if (tid < o) { s0[tid] += s0[tid + o]; s1[tid] += s1[tid + o]; }
            __syncthreads();
        }
        if (tid == 0) { out[b * 2 + 0] = s0[0]; out[b * 2 + 1] = s1[0]; }
    }
}

// ---------------- launch ----------------
extern "C" void kernel_launch(void* const* d_in, const int* in_sizes, int n_in,
                              void* d_out, int out_size) {
    const float* x     = (const float*)d_in[0];
    const float* pos   = (const float*)d_in[1];
    const float* ea    = (const float*)d_in[2];
    const int*   ei    = (const int*)  d_in[3];
    const int*   batch = (const int*)  d_in[4];
    const float* fcw   = (const float*)d_in[5];
    const float* w1 = (const float*)d_in[6];
    const float* w2 = (const float*)d_in[7];
    const float* w3 = (const float*)d_in[8];
    const float* w4 = (const float*)d_in[9];
    const float* w5 = (const float*)d_in[10];
    const float* w6 = (const float*)d_in[11];
    const float* w7 = (const float*)d_in[12];

    k_mega<<<NBLK, NTHR>>>(x, pos, ea, ei, batch, fcw,
                           w1, w2, w3, w4, w5, w6, w7, (float*)d_out);
}